// round 11
// baseline (speedup 1.0000x reference)
#include <cuda_runtime.h>
#include <cstdint>

// Problem sizes (fixed by the dataset; bounds for static scratch)
static constexpr int NN = 50000;
static constexpr int EE = 800000;

// Scratch (device globals: allocation-free per harness rules)
__device__ __align__(16) float g_x[(long long)NN * 128];  // mlp output [N,128]
__device__ float4 g_h1[NN];        // per-node logits, conv1 (4 heads)
__device__ float4 g_h2[NN];        // per-node logits, conv2 (4 heads)
__device__ int    g_cnt[NN];       // per-src degree
__device__ int    g_off[NN + 1];   // CSR row offsets
__device__ int    g_cur[NN];       // scatter cursors
__device__ int    g_sdst[EE];      // dst sorted by src

// ---------------------------------------------------------------------------
// Kernel 1: X = feat @ W_mlp + b_mlp  (SGEMM, packed f32x2 FMA, 1-deep
// register prefetch so GMEM latency hides under the math of the prior tile)
// BM=128, BN=128, BK=16, 256 threads, 8x8 micro-tile per thread
// ---------------------------------------------------------------------------
__global__ __launch_bounds__(256, 2) void gemm_mlp_kernel(
    const float* __restrict__ A,     // feat [N,256]
    const float* __restrict__ B,     // W_mlp [256,128] row-major (K x N)
    const float* __restrict__ bias,  // [128]
    int N)
{
    __shared__ float As[16][128];  // transposed A tile: As[k][m]
    __shared__ float Bs[16][128];  // Bs[k][n]

    const int tid  = threadIdx.x;
    const int brow = blockIdx.x * 128;
    const int tcol = (tid & 15) * 8;   // 0..120
    const int trow = (tid >> 4) * 8;   // 0..120

    // Per-thread GMEM load slots (2 float4 for A, 2 float4 for B)
    const int a_r0  = (tid * 2) >> 2;            // row in tile for slot 0
    const int a_c0  = ((tid * 2) & 3) * 4;       // k-offset for slot 0
    const int a_r1  = (tid * 2 + 1) >> 2;
    const int a_c1  = ((tid * 2 + 1) & 3) * 4;
    const int b_r0  = (tid * 2) >> 5;
    const int b_c0  = ((tid * 2) & 31) * 4;
    const int b_r1  = (tid * 2 + 1) >> 5;
    const int b_c1  = ((tid * 2 + 1) & 31) * 4;

    unsigned long long acc2[8][4];
#pragma unroll
    for (int i = 0; i < 8; i++)
#pragma unroll
        for (int j = 0; j < 4; j++) acc2[i][j] = 0ull;

    // Prefetch tile 0 into registers
    float4 pa0, pa1, pb0, pb1;
    {
        int gr0 = brow + a_r0, gr1 = brow + a_r1;
        pa0 = make_float4(0.f, 0.f, 0.f, 0.f);
        pa1 = make_float4(0.f, 0.f, 0.f, 0.f);
        if (gr0 < N) pa0 = *(const float4*)(A + (long long)gr0 * 256 + 0 + a_c0);
        if (gr1 < N) pa1 = *(const float4*)(A + (long long)gr1 * 256 + 0 + a_c1);
        pb0 = *(const float4*)(B + (long long)(0 + b_r0) * 128 + b_c0);
        pb1 = *(const float4*)(B + (long long)(0 + b_r1) * 128 + b_c1);
    }

    for (int k0 = 0; k0 < 256; k0 += 16) {
        // Store prefetched tile to smem
        As[a_c0 + 0][a_r0] = pa0.x;
        As[a_c0 + 1][a_r0] = pa0.y;
        As[a_c0 + 2][a_r0] = pa0.z;
        As[a_c0 + 3][a_r0] = pa0.w;
        As[a_c1 + 0][a_r1] = pa1.x;
        As[a_c1 + 1][a_r1] = pa1.y;
        As[a_c1 + 2][a_r1] = pa1.z;
        As[a_c1 + 3][a_r1] = pa1.w;
        *(float4*)&Bs[b_r0][b_c0] = pb0;
        *(float4*)&Bs[b_r1][b_c1] = pb1;
        __syncthreads();

        // Issue next tile's loads NOW — latency hides under this tile's math
        if (k0 + 16 < 256) {
            int kn = k0 + 16;
            int gr0 = brow + a_r0, gr1 = brow + a_r1;
            pa0 = make_float4(0.f, 0.f, 0.f, 0.f);
            pa1 = make_float4(0.f, 0.f, 0.f, 0.f);
            if (gr0 < N) pa0 = *(const float4*)(A + (long long)gr0 * 256 + kn + a_c0);
            if (gr1 < N) pa1 = *(const float4*)(A + (long long)gr1 * 256 + kn + a_c1);
            pb0 = *(const float4*)(B + (long long)(kn + b_r0) * 128 + b_c0);
            pb1 = *(const float4*)(B + (long long)(kn + b_r1) * 128 + b_c1);
        }

#pragma unroll
        for (int k = 0; k < 16; k++) {
            unsigned long long bn2[4];
            {
                float4 b0 = *(const float4*)&Bs[k][tcol];
                float4 b1 = *(const float4*)&Bs[k][tcol + 4];
                float2 p;
                p = make_float2(b0.x, b0.y); bn2[0] = *reinterpret_cast<unsigned long long*>(&p);
                p = make_float2(b0.z, b0.w); bn2[1] = *reinterpret_cast<unsigned long long*>(&p);
                p = make_float2(b1.x, b1.y); bn2[2] = *reinterpret_cast<unsigned long long*>(&p);
                p = make_float2(b1.z, b1.w); bn2[3] = *reinterpret_cast<unsigned long long*>(&p);
            }
            float am[8];
            {
                float4 a0 = *(const float4*)&As[k][trow];
                float4 a1 = *(const float4*)&As[k][trow + 4];
                am[0] = a0.x; am[1] = a0.y; am[2] = a0.z; am[3] = a0.w;
                am[4] = a1.x; am[5] = a1.y; am[6] = a1.z; am[7] = a1.w;
            }
#pragma unroll
            for (int i = 0; i < 8; i++) {
                unsigned long long am2;
                asm("mov.b64 %0, {%1, %1};" : "=l"(am2) : "f"(am[i]));
#pragma unroll
                for (int j = 0; j < 4; j++) {
                    asm("fma.rn.f32x2 %0, %1, %2, %3;"
                        : "=l"(acc2[i][j])
                        : "l"(am2), "l"(bn2[j]), "l"(acc2[i][j]));
                }
            }
        }
        __syncthreads();
    }

#pragma unroll
    for (int i = 0; i < 8; i++) {
        int gr = brow + trow + i;
        if (gr < N) {
#pragma unroll
            for (int j = 0; j < 2; j++) {
                float2 p0 = *reinterpret_cast<float2*>(&acc2[i][2 * j + 0]);
                float2 p1 = *reinterpret_cast<float2*>(&acc2[i][2 * j + 1]);
                float4 v;
                v.x = p0.x + bias[tcol + 4 * j + 0];
                v.y = p0.y + bias[tcol + 4 * j + 1];
                v.z = p1.x + bias[tcol + 4 * j + 2];
                v.w = p1.y + bias[tcol + 4 * j + 3];
                *(float4*)(g_x + (long long)gr * 128 + tcol + 4 * j) = v;
            }
        }
    }
}

// ---------------------------------------------------------------------------
// Kernel 2: h1 = feat @ W1^T + b1, h2 = feat @ W2^T + b2   (one warp / node)
// ---------------------------------------------------------------------------
__global__ __launch_bounds__(256) void h_kernel(
    const float* __restrict__ feat,
    const float* __restrict__ W1, const float* __restrict__ b1,
    const float* __restrict__ W2, const float* __restrict__ b2,
    int N)
{
    int warp = (blockIdx.x * blockDim.x + threadIdx.x) >> 5;
    if (warp >= N) return;
    int lane = threadIdx.x & 31;

    float a[4] = {0.f, 0.f, 0.f, 0.f};
    float b[4] = {0.f, 0.f, 0.f, 0.f};
    const float* frow = feat + (long long)warp * 256;
#pragma unroll
    for (int kk = 0; kk < 8; kk++) {
        int k   = lane + kk * 32;
        float f = frow[k];
#pragma unroll
        for (int j = 0; j < 4; j++) {
            a[j] = fmaf(f, __ldg(W1 + j * 256 + k), a[j]);
            b[j] = fmaf(f, __ldg(W2 + j * 256 + k), b[j]);
        }
    }
#pragma unroll
    for (int off = 16; off; off >>= 1) {
#pragma unroll
        for (int j = 0; j < 4; j++) {
            a[j] += __shfl_xor_sync(0xFFFFFFFFu, a[j], off);
            b[j] += __shfl_xor_sync(0xFFFFFFFFu, b[j], off);
        }
    }
    if (lane == 0) {
        g_h1[warp] = make_float4(a[0] + b1[0], a[1] + b1[1], a[2] + b1[2], a[3] + b1[3]);
        g_h2[warp] = make_float4(b[0] + b2[0], b[1] + b2[1], b[2] + b2[2], b[3] + b2[3]);
    }
}

// ---------------------------------------------------------------------------
// CSR build: zero counts, count degrees, scan, scatter dst by src
// ---------------------------------------------------------------------------
__global__ void zero_cnt_kernel(int N)
{
    int i = blockIdx.x * blockDim.x + threadIdx.x;
    if (i < N) g_cnt[i] = 0;
}

__global__ void count_kernel(const int* __restrict__ ei, int E)
{
    int e = blockIdx.x * blockDim.x + threadIdx.x;
    if (e < E) atomicAdd(&g_cnt[ei[e]], 1);
}

__global__ __launch_bounds__(1024) void scan_kernel(int N)
{
    __shared__ int warp_sums[32];
    __shared__ int s_carry;
    const int tid = threadIdx.x, lane = tid & 31, wid = tid >> 5;
    if (tid == 0) s_carry = 0;
    __syncthreads();

    for (int base = 0; base < N; base += 1024) {
        int i = base + tid;
        int v = (i < N) ? g_cnt[i] : 0;
        int x = v;
#pragma unroll
        for (int o = 1; o < 32; o <<= 1) {
            int y = __shfl_up_sync(0xFFFFFFFFu, x, o);
            if (lane >= o) x += y;
        }
        if (lane == 31) warp_sums[wid] = x;
        __syncthreads();
        if (wid == 0) {
            int s = warp_sums[lane];
#pragma unroll
            for (int o = 1; o < 32; o <<= 1) {
                int y = __shfl_up_sync(0xFFFFFFFFu, s, o);
                if (lane >= o) s += y;
            }
            warp_sums[lane] = s;
        }
        __syncthreads();
        int warp_off = (wid == 0) ? 0 : warp_sums[wid - 1];
        int excl = s_carry + warp_off + x - v;
        if (i < N) { g_off[i] = excl; g_cur[i] = excl; }
        int chunk_total = warp_sums[31];
        __syncthreads();
        if (tid == 0) s_carry += chunk_total;
        __syncthreads();
    }
    if (tid == 0) g_off[N] = s_carry;
}

__global__ void scatter_kernel(const int* __restrict__ ei, int E)
{
    int e = blockIdx.x * blockDim.x + threadIdx.x;
    if (e < E) {
        int s = ei[e];
        int d = ei[E + e];
        int pos = atomicAdd(&g_cur[s], 1);
        g_sdst[pos] = d;
    }
}

// ---------------------------------------------------------------------------
// Kernel 4: aggregate.  One warp per node, no atomics, 2-edge ILP.
// (Round-4 known-good version, unchanged.)
// ---------------------------------------------------------------------------
__global__ __launch_bounds__(256) void agg_kernel(
    const float* __restrict__ eps,
    float* __restrict__ OUT,
    int N)
{
    int node = (blockIdx.x * blockDim.x + threadIdx.x) >> 5;
    if (node >= N) return;
    int lane = threadIdx.x & 31;
    int head = lane >> 3;           // 4 heads, 8 lanes each
    int j    = lane * 4;            // feature offset (float4)

    float4 ha = g_h1[node];
    float ha_h = (head < 2) ? (head == 0 ? ha.x : ha.y)
                            : (head == 2 ? ha.z : ha.w);

    int i   = g_off[node];
    int end = g_off[node + 1];

    float4 acc0 = make_float4(0.f, 0.f, 0.f, 0.f);
    float4 acc1 = make_float4(0.f, 0.f, 0.f, 0.f);

    for (; i + 2 <= end; i += 2) {
        int d0 = __ldg(&g_sdst[i]);
        int d1 = __ldg(&g_sdst[i + 1]);
        float4 hb0 = g_h2[d0];
        float4 hb1 = g_h2[d1];
        float v0 = ha_h + ((head < 2) ? (head == 0 ? hb0.x : hb0.y)
                                      : (head == 2 ? hb0.z : hb0.w));
        float v1 = ha_h + ((head < 2) ? (head == 0 ? hb1.x : hb1.y)
                                      : (head == 2 ? hb1.z : hb1.w));
        if (v0 > 0.f) {
            float4 xv = *(const float4*)(g_x + (long long)d0 * 128 + j);
            acc0.x = fmaf(v0, xv.x, acc0.x);
            acc0.y = fmaf(v0, xv.y, acc0.y);
            acc0.z = fmaf(v0, xv.z, acc0.z);
            acc0.w = fmaf(v0, xv.w, acc0.w);
        }
        if (v1 > 0.f) {
            float4 xv = *(const float4*)(g_x + (long long)d1 * 128 + j);
            acc1.x = fmaf(v1, xv.x, acc1.x);
            acc1.y = fmaf(v1, xv.y, acc1.y);
            acc1.z = fmaf(v1, xv.z, acc1.z);
            acc1.w = fmaf(v1, xv.w, acc1.w);
        }
    }
    if (i < end) {  // tail edge
        int d0 = __ldg(&g_sdst[i]);
        float4 hb0 = g_h2[d0];
        float v0 = ha_h + ((head < 2) ? (head == 0 ? hb0.x : hb0.y)
                                      : (head == 2 ? hb0.z : hb0.w));
        if (v0 > 0.f) {
            float4 xv = *(const float4*)(g_x + (long long)d0 * 128 + j);
            acc0.x = fmaf(v0, xv.x, acc0.x);
            acc0.y = fmaf(v0, xv.y, acc0.y);
            acc0.z = fmaf(v0, xv.z, acc0.z);
            acc0.w = fmaf(v0, xv.w, acc0.w);
        }
    }

    float e0 = eps[0];
    float4 xs = *(const float4*)(g_x + (long long)node * 128 + j);
    float4 o;
    o.x = fmaf(e0, xs.x, acc0.x + acc1.x);
    o.y = fmaf(e0, xs.y, acc0.y + acc1.y);
    o.z = fmaf(e0, xs.z, acc0.z + acc1.z);
    o.w = fmaf(e0, xs.w, acc0.w + acc1.w);
    *(float4*)(OUT + (long long)node * 128 + j) = o;
}

// ---------------------------------------------------------------------------
extern "C" void kernel_launch(void* const* d_in, const int* in_sizes, int n_in,
                              void* d_out, int out_size)
{
    const float* feat  = (const float*)d_in[0];
    const int*   ei    = (const int*)d_in[1];
    const float* W_mlp = (const float*)d_in[2];
    const float* b_mlp = (const float*)d_in[3];
    const float* W1    = (const float*)d_in[4];
    const float* b1    = (const float*)d_in[5];
    const float* W2    = (const float*)d_in[6];
    const float* b2    = (const float*)d_in[7];
    const float* eps   = (const float*)d_in[8];

    const int N = in_sizes[0] / 256;
    const int E = in_sizes[1] / 2;
    float* out = (float*)d_out;

    // One-time side stream + fork/join events (host objects, no device mem)
    static cudaStream_t s_side = nullptr;
    static cudaEvent_t  ev_fork = nullptr, ev_join = nullptr;
    if (!s_side) {
        cudaStreamCreateWithFlags(&s_side, cudaStreamNonBlocking);
        cudaEventCreateWithFlags(&ev_fork, cudaEventDisableTiming);
        cudaEventCreateWithFlags(&ev_join, cudaEventDisableTiming);
    }

    // Fork: h projections + CSR build on side stream, hidden under the GEMM.
    cudaEventRecord(ev_fork, 0);
    cudaStreamWaitEvent(s_side, ev_fork, 0);

    h_kernel<<<(N + 7) / 8, 256, 0, s_side>>>(feat, W1, b1, W2, b2, N);
    zero_cnt_kernel<<<(N + 511) / 512, 512, 0, s_side>>>(N);
    count_kernel<<<(E + 255) / 256, 256, 0, s_side>>>(ei, E);
    scan_kernel<<<1, 1024, 0, s_side>>>(N);
    scatter_kernel<<<(E + 255) / 256, 256, 0, s_side>>>(ei, E);
    cudaEventRecord(ev_join, s_side);

    // Dense chain on capture (NULL) stream.
    gemm_mlp_kernel<<<(N + 127) / 128, 256>>>(feat, W_mlp, b_mlp, N);

    // Join, then atomic-free aggregation + epilogue.
    cudaStreamWaitEvent(0, ev_join, 0);
    agg_kernel<<<(N + 7) / 8, 256>>>(eps, out, N);
}

// round 12
// speedup vs baseline: 1.0147x; 1.0147x over previous
#include <cuda_runtime.h>
#include <cstdint>

// Problem sizes (fixed by the dataset; bounds for static scratch)
static constexpr int NN = 50000;
static constexpr int EE = 800000;

// Scratch (device globals: allocation-free per harness rules)
__device__ __align__(16) float g_x[(long long)NN * 128];  // mlp output [N,128]
__device__ float4 g_h1[NN];        // per-node logits, conv1 (4 heads)
__device__ float4 g_h2[NN];        // per-node logits, conv2 (4 heads)
__device__ int    g_cnt[NN];       // per-src degree
__device__ int    g_off[NN + 1];   // CSR row offsets
__device__ int    g_cur[NN];       // scatter cursors
__device__ int    g_sdst[EE];      // dst sorted by src
__device__ int    g_bsum[64];      // per-block sums for the parallel scan

// ---------------------------------------------------------------------------
// Kernel 1: X = feat @ W_mlp + b_mlp  (SGEMM, packed f32x2 FMA, 1-deep
// register prefetch so GMEM latency hides under the math of the prior tile)
// BM=128, BN=128, BK=16, 256 threads, 8x8 micro-tile per thread
// ---------------------------------------------------------------------------
__global__ __launch_bounds__(256, 2) void gemm_mlp_kernel(
    const float* __restrict__ A,     // feat [N,256]
    const float* __restrict__ B,     // W_mlp [256,128] row-major (K x N)
    const float* __restrict__ bias,  // [128]
    int N)
{
    __shared__ float As[16][128];  // transposed A tile: As[k][m]
    __shared__ float Bs[16][128];  // Bs[k][n]

    const int tid  = threadIdx.x;
    const int brow = blockIdx.x * 128;
    const int tcol = (tid & 15) * 8;   // 0..120
    const int trow = (tid >> 4) * 8;   // 0..120

    const int a_r0  = (tid * 2) >> 2;
    const int a_c0  = ((tid * 2) & 3) * 4;
    const int a_r1  = (tid * 2 + 1) >> 2;
    const int a_c1  = ((tid * 2 + 1) & 3) * 4;
    const int b_r0  = (tid * 2) >> 5;
    const int b_c0  = ((tid * 2) & 31) * 4;
    const int b_r1  = (tid * 2 + 1) >> 5;
    const int b_c1  = ((tid * 2 + 1) & 31) * 4;

    unsigned long long acc2[8][4];
#pragma unroll
    for (int i = 0; i < 8; i++)
#pragma unroll
        for (int j = 0; j < 4; j++) acc2[i][j] = 0ull;

    float4 pa0, pa1, pb0, pb1;
    {
        int gr0 = brow + a_r0, gr1 = brow + a_r1;
        pa0 = make_float4(0.f, 0.f, 0.f, 0.f);
        pa1 = make_float4(0.f, 0.f, 0.f, 0.f);
        if (gr0 < N) pa0 = *(const float4*)(A + (long long)gr0 * 256 + 0 + a_c0);
        if (gr1 < N) pa1 = *(const float4*)(A + (long long)gr1 * 256 + 0 + a_c1);
        pb0 = *(const float4*)(B + (long long)(0 + b_r0) * 128 + b_c0);
        pb1 = *(const float4*)(B + (long long)(0 + b_r1) * 128 + b_c1);
    }

    for (int k0 = 0; k0 < 256; k0 += 16) {
        As[a_c0 + 0][a_r0] = pa0.x;
        As[a_c0 + 1][a_r0] = pa0.y;
        As[a_c0 + 2][a_r0] = pa0.z;
        As[a_c0 + 3][a_r0] = pa0.w;
        As[a_c1 + 0][a_r1] = pa1.x;
        As[a_c1 + 1][a_r1] = pa1.y;
        As[a_c1 + 2][a_r1] = pa1.z;
        As[a_c1 + 3][a_r1] = pa1.w;
        *(float4*)&Bs[b_r0][b_c0] = pb0;
        *(float4*)&Bs[b_r1][b_c1] = pb1;
        __syncthreads();

        if (k0 + 16 < 256) {
            int kn = k0 + 16;
            int gr0 = brow + a_r0, gr1 = brow + a_r1;
            pa0 = make_float4(0.f, 0.f, 0.f, 0.f);
            pa1 = make_float4(0.f, 0.f, 0.f, 0.f);
            if (gr0 < N) pa0 = *(const float4*)(A + (long long)gr0 * 256 + kn + a_c0);
            if (gr1 < N) pa1 = *(const float4*)(A + (long long)gr1 * 256 + kn + a_c1);
            pb0 = *(const float4*)(B + (long long)(kn + b_r0) * 128 + b_c0);
            pb1 = *(const float4*)(B + (long long)(kn + b_r1) * 128 + b_c1);
        }

#pragma unroll
        for (int k = 0; k < 16; k++) {
            unsigned long long bn2[4];
            {
                float4 b0 = *(const float4*)&Bs[k][tcol];
                float4 b1 = *(const float4*)&Bs[k][tcol + 4];
                float2 p;
                p = make_float2(b0.x, b0.y); bn2[0] = *reinterpret_cast<unsigned long long*>(&p);
                p = make_float2(b0.z, b0.w); bn2[1] = *reinterpret_cast<unsigned long long*>(&p);
                p = make_float2(b1.x, b1.y); bn2[2] = *reinterpret_cast<unsigned long long*>(&p);
                p = make_float2(b1.z, b1.w); bn2[3] = *reinterpret_cast<unsigned long long*>(&p);
            }
            float am[8];
            {
                float4 a0 = *(const float4*)&As[k][trow];
                float4 a1 = *(const float4*)&As[k][trow + 4];
                am[0] = a0.x; am[1] = a0.y; am[2] = a0.z; am[3] = a0.w;
                am[4] = a1.x; am[5] = a1.y; am[6] = a1.z; am[7] = a1.w;
            }
#pragma unroll
            for (int i = 0; i < 8; i++) {
                unsigned long long am2;
                asm("mov.b64 %0, {%1, %1};" : "=l"(am2) : "f"(am[i]));
#pragma unroll
                for (int j = 0; j < 4; j++) {
                    asm("fma.rn.f32x2 %0, %1, %2, %3;"
                        : "=l"(acc2[i][j])
                        : "l"(am2), "l"(bn2[j]), "l"(acc2[i][j]));
                }
            }
        }
        __syncthreads();
    }

#pragma unroll
    for (int i = 0; i < 8; i++) {
        int gr = brow + trow + i;
        if (gr < N) {
#pragma unroll
            for (int j = 0; j < 2; j++) {
                float2 p0 = *reinterpret_cast<float2*>(&acc2[i][2 * j + 0]);
                float2 p1 = *reinterpret_cast<float2*>(&acc2[i][2 * j + 1]);
                float4 v;
                v.x = p0.x + bias[tcol + 4 * j + 0];
                v.y = p0.y + bias[tcol + 4 * j + 1];
                v.z = p1.x + bias[tcol + 4 * j + 2];
                v.w = p1.y + bias[tcol + 4 * j + 3];
                *(float4*)(g_x + (long long)gr * 128 + tcol + 4 * j) = v;
            }
        }
    }
}

// ---------------------------------------------------------------------------
// Kernel 2: h1 = feat @ W1^T + b1, h2 = feat @ W2^T + b2   (one warp / node)
// ---------------------------------------------------------------------------
__global__ __launch_bounds__(256) void h_kernel(
    const float* __restrict__ feat,
    const float* __restrict__ W1, const float* __restrict__ b1,
    const float* __restrict__ W2, const float* __restrict__ b2,
    int N)
{
    int warp = (blockIdx.x * blockDim.x + threadIdx.x) >> 5;
    if (warp >= N) return;
    int lane = threadIdx.x & 31;

    float a[4] = {0.f, 0.f, 0.f, 0.f};
    float b[4] = {0.f, 0.f, 0.f, 0.f};
    const float* frow = feat + (long long)warp * 256;
#pragma unroll
    for (int kk = 0; kk < 8; kk++) {
        int k   = lane + kk * 32;
        float f = frow[k];
#pragma unroll
        for (int j = 0; j < 4; j++) {
            a[j] = fmaf(f, __ldg(W1 + j * 256 + k), a[j]);
            b[j] = fmaf(f, __ldg(W2 + j * 256 + k), b[j]);
        }
    }
#pragma unroll
    for (int off = 16; off; off >>= 1) {
#pragma unroll
        for (int j = 0; j < 4; j++) {
            a[j] += __shfl_xor_sync(0xFFFFFFFFu, a[j], off);
            b[j] += __shfl_xor_sync(0xFFFFFFFFu, b[j], off);
        }
    }
    if (lane == 0) {
        g_h1[warp] = make_float4(a[0] + b1[0], a[1] + b1[1], a[2] + b1[2], a[3] + b1[3]);
        g_h2[warp] = make_float4(b[0] + b2[0], b[1] + b2[1], b[2] + b2[2], b[3] + b2[3]);
    }
}

// ---------------------------------------------------------------------------
// CSR build: zero, count, PARALLEL 3-pass scan, scatter
// ---------------------------------------------------------------------------
__global__ void zero_cnt_kernel(int N)
{
    int i = blockIdx.x * blockDim.x + threadIdx.x;
    if (i < N) g_cnt[i] = 0;
}

__global__ void count_kernel(const int* __restrict__ ei, int E)
{
    int e = blockIdx.x * blockDim.x + threadIdx.x;
    if (e < E) atomicAdd(&g_cnt[ei[e]], 1);
}

// Pass 1: per-1024-element block — in-block exclusive prefix -> g_off,
// block total -> g_bsum[b].  256 threads, 4 elements/thread.
__global__ __launch_bounds__(256) void scan1_kernel(int N)
{
    __shared__ int wsum[8];
    const int b = blockIdx.x;
    const int tid = threadIdx.x, lane = tid & 31, wid = tid >> 5;
    const int base = b * 1024 + tid * 4;

    int v0 = (base + 0 < N) ? g_cnt[base + 0] : 0;
    int v1 = (base + 1 < N) ? g_cnt[base + 1] : 0;
    int v2 = (base + 2 < N) ? g_cnt[base + 2] : 0;
    int v3 = (base + 3 < N) ? g_cnt[base + 3] : 0;
    int t = v0 + v1 + v2 + v3;

    int x = t;
#pragma unroll
    for (int o = 1; o < 32; o <<= 1) {
        int y = __shfl_up_sync(0xFFFFFFFFu, x, o);
        if (lane >= o) x += y;
    }
    if (lane == 31) wsum[wid] = x;
    __syncthreads();
    if (wid == 0 && lane < 8) {
        int s = wsum[lane];
#pragma unroll
        for (int o = 1; o < 8; o <<= 1) {
            int y = __shfl_up_sync(0xFFu, s, o);
            if (lane >= o) s += y;
        }
        wsum[lane] = s;
    }
    __syncthreads();

    int excl = ((wid > 0) ? wsum[wid - 1] : 0) + x - t;
    if (base + 0 < N) g_off[base + 0] = excl;
    if (base + 1 < N) g_off[base + 1] = excl + v0;
    if (base + 2 < N) g_off[base + 2] = excl + v0 + v1;
    if (base + 3 < N) g_off[base + 3] = excl + v0 + v1 + v2;
    if (tid == 0) g_bsum[b] = wsum[7];   // block total
}

// Pass 2: exclusive scan of <=64 block totals (one block, 64 threads)
__global__ void scan2_kernel(int NB)
{
    __shared__ int ws[2];
    const int tid = threadIdx.x, lane = tid & 31, wid = tid >> 5;
    int v = (tid < NB) ? g_bsum[tid] : 0;
    int x = v;
#pragma unroll
    for (int o = 1; o < 32; o <<= 1) {
        int y = __shfl_up_sync(0xFFFFFFFFu, x, o);
        if (lane >= o) x += y;
    }
    if (lane == 31) ws[wid] = x;
    __syncthreads();
    int incl = x + ((wid == 1) ? ws[0] : 0);
    if (tid < NB) g_bsum[tid] = incl - v;  // exclusive block offset
}

// Pass 3: add block offsets, init cursors, set sentinel
__global__ void scan3_kernel(int N, int E)
{
    int i = blockIdx.x * blockDim.x + threadIdx.x;
    if (i < N) {
        int o = g_off[i] + g_bsum[i >> 10];
        g_off[i] = o;
        g_cur[i] = o;
    }
    if (i == 0) g_off[N] = E;
}

__global__ void scatter_kernel(const int* __restrict__ ei, int E)
{
    int e = blockIdx.x * blockDim.x + threadIdx.x;
    if (e < E) {
        int s = ei[e];
        int d = ei[E + e];
        int pos = atomicAdd(&g_cur[s], 1);
        g_sdst[pos] = d;
    }
}

// ---------------------------------------------------------------------------
// Kernel 4: aggregate.  One warp per node, no atomics, 2-edge ILP.
// (Round-4 known-good version, unchanged.)
// ---------------------------------------------------------------------------
__global__ __launch_bounds__(256) void agg_kernel(
    const float* __restrict__ eps,
    float* __restrict__ OUT,
    int N)
{
    int node = (blockIdx.x * blockDim.x + threadIdx.x) >> 5;
    if (node >= N) return;
    int lane = threadIdx.x & 31;
    int head = lane >> 3;           // 4 heads, 8 lanes each
    int j    = lane * 4;            // feature offset (float4)

    float4 ha = g_h1[node];
    float ha_h = (head < 2) ? (head == 0 ? ha.x : ha.y)
                            : (head == 2 ? ha.z : ha.w);

    int i   = g_off[node];
    int end = g_off[node + 1];

    float4 acc0 = make_float4(0.f, 0.f, 0.f, 0.f);
    float4 acc1 = make_float4(0.f, 0.f, 0.f, 0.f);

    for (; i + 2 <= end; i += 2) {
        int d0 = __ldg(&g_sdst[i]);
        int d1 = __ldg(&g_sdst[i + 1]);
        float4 hb0 = g_h2[d0];
        float4 hb1 = g_h2[d1];
        float v0 = ha_h + ((head < 2) ? (head == 0 ? hb0.x : hb0.y)
                                      : (head == 2 ? hb0.z : hb0.w));
        float v1 = ha_h + ((head < 2) ? (head == 0 ? hb1.x : hb1.y)
                                      : (head == 2 ? hb1.z : hb1.w));
        if (v0 > 0.f) {
            float4 xv = *(const float4*)(g_x + (long long)d0 * 128 + j);
            acc0.x = fmaf(v0, xv.x, acc0.x);
            acc0.y = fmaf(v0, xv.y, acc0.y);
            acc0.z = fmaf(v0, xv.z, acc0.z);
            acc0.w = fmaf(v0, xv.w, acc0.w);
        }
        if (v1 > 0.f) {
            float4 xv = *(const float4*)(g_x + (long long)d1 * 128 + j);
            acc1.x = fmaf(v1, xv.x, acc1.x);
            acc1.y = fmaf(v1, xv.y, acc1.y);
            acc1.z = fmaf(v1, xv.z, acc1.z);
            acc1.w = fmaf(v1, xv.w, acc1.w);
        }
    }
    if (i < end) {  // tail edge
        int d0 = __ldg(&g_sdst[i]);
        float4 hb0 = g_h2[d0];
        float v0 = ha_h + ((head < 2) ? (head == 0 ? hb0.x : hb0.y)
                                      : (head == 2 ? hb0.z : hb0.w));
        if (v0 > 0.f) {
            float4 xv = *(const float4*)(g_x + (long long)d0 * 128 + j);
            acc0.x = fmaf(v0, xv.x, acc0.x);
            acc0.y = fmaf(v0, xv.y, acc0.y);
            acc0.z = fmaf(v0, xv.z, acc0.z);
            acc0.w = fmaf(v0, xv.w, acc0.w);
        }
    }

    float e0 = eps[0];
    float4 xs = *(const float4*)(g_x + (long long)node * 128 + j);
    float4 o;
    o.x = fmaf(e0, xs.x, acc0.x + acc1.x);
    o.y = fmaf(e0, xs.y, acc0.y + acc1.y);
    o.z = fmaf(e0, xs.z, acc0.z + acc1.z);
    o.w = fmaf(e0, xs.w, acc0.w + acc1.w);
    *(float4*)(OUT + (long long)node * 128 + j) = o;
}

// ---------------------------------------------------------------------------
extern "C" void kernel_launch(void* const* d_in, const int* in_sizes, int n_in,
                              void* d_out, int out_size)
{
    const float* feat  = (const float*)d_in[0];
    const int*   ei    = (const int*)d_in[1];
    const float* W_mlp = (const float*)d_in[2];
    const float* b_mlp = (const float*)d_in[3];
    const float* W1    = (const float*)d_in[4];
    const float* b1    = (const float*)d_in[5];
    const float* W2    = (const float*)d_in[6];
    const float* b2    = (const float*)d_in[7];
    const float* eps   = (const float*)d_in[8];

    const int N = in_sizes[0] / 256;
    const int E = in_sizes[1] / 2;
    float* out = (float*)d_out;

    // One-time side stream + fork/join events (host objects, no device mem)
    static cudaStream_t s_side = nullptr;
    static cudaEvent_t  ev_fork = nullptr, ev_join = nullptr;
    if (!s_side) {
        cudaStreamCreateWithFlags(&s_side, cudaStreamNonBlocking);
        cudaEventCreateWithFlags(&ev_fork, cudaEventDisableTiming);
        cudaEventCreateWithFlags(&ev_join, cudaEventDisableTiming);
    }

    const int NB = (N + 1023) / 1024;   // scan blocks (<=64 for N<=65536)

    // Fork: h projections + CSR build on side stream, hidden under the GEMM.
    cudaEventRecord(ev_fork, 0);
    cudaStreamWaitEvent(s_side, ev_fork, 0);

    h_kernel<<<(N + 7) / 8, 256, 0, s_side>>>(feat, W1, b1, W2, b2, N);
    zero_cnt_kernel<<<(N + 511) / 512, 512, 0, s_side>>>(N);
    count_kernel<<<(E + 255) / 256, 256, 0, s_side>>>(ei, E);
    scan1_kernel<<<NB, 256, 0, s_side>>>(N);
    scan2_kernel<<<1, 64, 0, s_side>>>(NB);
    scan3_kernel<<<(N + 255) / 256, 256, 0, s_side>>>(N, E);
    scatter_kernel<<<(E + 255) / 256, 256, 0, s_side>>>(ei, E);
    cudaEventRecord(ev_join, s_side);

    // Dense chain on capture (NULL) stream.
    gemm_mlp_kernel<<<(N + 127) / 128, 256>>>(feat, W_mlp, b_mlp, N);

    // Join, then atomic-free aggregation + epilogue.
    cudaStreamWaitEvent(0, ev_join, 0);
    agg_kernel<<<(N + 7) / 8, 256>>>(eps, out, N);
}

// round 13
// speedup vs baseline: 1.0566x; 1.0413x over previous
#include <cuda_runtime.h>
#include <cstdint>

// Problem sizes (fixed by the dataset; bounds for static scratch)
static constexpr int NN = 50000;
static constexpr int EE = 800000;

// Scratch (device globals: allocation-free per harness rules)
__device__ __align__(16) float g_x[(long long)NN * 128];  // mlp output [N,128]
__device__ float4 g_h1[NN];        // per-node logits, conv1 (4 heads)
__device__ float4 g_h2[NN];        // per-node logits, conv2 (4 heads)
__device__ int    g_cnt[NN];       // per-src degree
__device__ int    g_off[NN + 1];   // CSR row offsets
__device__ int    g_cur[NN];       // scatter cursors
__device__ int    g_sdst[EE];      // dst sorted by src
__device__ int    g_bsum[64];      // per-block sums for the parallel scan

// ---------------------------------------------------------------------------
// Kernel 1: X = feat @ W_mlp + b_mlp  (SGEMM, packed f32x2 FMA, 1-deep
// register prefetch so GMEM latency hides under the math of the prior tile)
// BM=128, BN=128, BK=16, 256 threads, 8x8 micro-tile per thread
// ---------------------------------------------------------------------------
__global__ __launch_bounds__(256, 2) void gemm_mlp_kernel(
    const float* __restrict__ A,     // feat [N,256]
    const float* __restrict__ B,     // W_mlp [256,128] row-major (K x N)
    const float* __restrict__ bias,  // [128]
    int N)
{
    __shared__ float As[16][128];  // transposed A tile: As[k][m]
    __shared__ float Bs[16][128];  // Bs[k][n]

    const int tid  = threadIdx.x;
    const int brow = blockIdx.x * 128;
    const int tcol = (tid & 15) * 8;   // 0..120
    const int trow = (tid >> 4) * 8;   // 0..120

    const int a_r0  = (tid * 2) >> 2;
    const int a_c0  = ((tid * 2) & 3) * 4;
    const int a_r1  = (tid * 2 + 1) >> 2;
    const int a_c1  = ((tid * 2 + 1) & 3) * 4;
    const int b_r0  = (tid * 2) >> 5;
    const int b_c0  = ((tid * 2) & 31) * 4;
    const int b_r1  = (tid * 2 + 1) >> 5;
    const int b_c1  = ((tid * 2 + 1) & 31) * 4;

    unsigned long long acc2[8][4];
#pragma unroll
    for (int i = 0; i < 8; i++)
#pragma unroll
        for (int j = 0; j < 4; j++) acc2[i][j] = 0ull;

    float4 pa0, pa1, pb0, pb1;
    {
        int gr0 = brow + a_r0, gr1 = brow + a_r1;
        pa0 = make_float4(0.f, 0.f, 0.f, 0.f);
        pa1 = make_float4(0.f, 0.f, 0.f, 0.f);
        if (gr0 < N) pa0 = *(const float4*)(A + (long long)gr0 * 256 + 0 + a_c0);
        if (gr1 < N) pa1 = *(const float4*)(A + (long long)gr1 * 256 + 0 + a_c1);
        pb0 = *(const float4*)(B + (long long)(0 + b_r0) * 128 + b_c0);
        pb1 = *(const float4*)(B + (long long)(0 + b_r1) * 128 + b_c1);
    }

    for (int k0 = 0; k0 < 256; k0 += 16) {
        As[a_c0 + 0][a_r0] = pa0.x;
        As[a_c0 + 1][a_r0] = pa0.y;
        As[a_c0 + 2][a_r0] = pa0.z;
        As[a_c0 + 3][a_r0] = pa0.w;
        As[a_c1 + 0][a_r1] = pa1.x;
        As[a_c1 + 1][a_r1] = pa1.y;
        As[a_c1 + 2][a_r1] = pa1.z;
        As[a_c1 + 3][a_r1] = pa1.w;
        *(float4*)&Bs[b_r0][b_c0] = pb0;
        *(float4*)&Bs[b_r1][b_c1] = pb1;
        __syncthreads();

        if (k0 + 16 < 256) {
            int kn = k0 + 16;
            int gr0 = brow + a_r0, gr1 = brow + a_r1;
            pa0 = make_float4(0.f, 0.f, 0.f, 0.f);
            pa1 = make_float4(0.f, 0.f, 0.f, 0.f);
            if (gr0 < N) pa0 = *(const float4*)(A + (long long)gr0 * 256 + kn + a_c0);
            if (gr1 < N) pa1 = *(const float4*)(A + (long long)gr1 * 256 + kn + a_c1);
            pb0 = *(const float4*)(B + (long long)(kn + b_r0) * 128 + b_c0);
            pb1 = *(const float4*)(B + (long long)(kn + b_r1) * 128 + b_c1);
        }

#pragma unroll
        for (int k = 0; k < 16; k++) {
            unsigned long long bn2[4];
            {
                float4 b0 = *(const float4*)&Bs[k][tcol];
                float4 b1 = *(const float4*)&Bs[k][tcol + 4];
                float2 p;
                p = make_float2(b0.x, b0.y); bn2[0] = *reinterpret_cast<unsigned long long*>(&p);
                p = make_float2(b0.z, b0.w); bn2[1] = *reinterpret_cast<unsigned long long*>(&p);
                p = make_float2(b1.x, b1.y); bn2[2] = *reinterpret_cast<unsigned long long*>(&p);
                p = make_float2(b1.z, b1.w); bn2[3] = *reinterpret_cast<unsigned long long*>(&p);
            }
            float am[8];
            {
                float4 a0 = *(const float4*)&As[k][trow];
                float4 a1 = *(const float4*)&As[k][trow + 4];
                am[0] = a0.x; am[1] = a0.y; am[2] = a0.z; am[3] = a0.w;
                am[4] = a1.x; am[5] = a1.y; am[6] = a1.z; am[7] = a1.w;
            }
#pragma unroll
            for (int i = 0; i < 8; i++) {
                unsigned long long am2;
                asm("mov.b64 %0, {%1, %1};" : "=l"(am2) : "f"(am[i]));
#pragma unroll
                for (int j = 0; j < 4; j++) {
                    asm("fma.rn.f32x2 %0, %1, %2, %3;"
                        : "=l"(acc2[i][j])
                        : "l"(am2), "l"(bn2[j]), "l"(acc2[i][j]));
                }
            }
        }
        __syncthreads();
    }

#pragma unroll
    for (int i = 0; i < 8; i++) {
        int gr = brow + trow + i;
        if (gr < N) {
#pragma unroll
            for (int j = 0; j < 2; j++) {
                float2 p0 = *reinterpret_cast<float2*>(&acc2[i][2 * j + 0]);
                float2 p1 = *reinterpret_cast<float2*>(&acc2[i][2 * j + 1]);
                float4 v;
                v.x = p0.x + bias[tcol + 4 * j + 0];
                v.y = p0.y + bias[tcol + 4 * j + 1];
                v.z = p1.x + bias[tcol + 4 * j + 2];
                v.w = p1.y + bias[tcol + 4 * j + 3];
                *(float4*)(g_x + (long long)gr * 128 + tcol + 4 * j) = v;
            }
        }
    }
}

// ---------------------------------------------------------------------------
// Kernel 2: h1 = feat @ W1^T + b1, h2 = feat @ W2^T + b2   (one warp / node)
// ---------------------------------------------------------------------------
__global__ __launch_bounds__(256) void h_kernel(
    const float* __restrict__ feat,
    const float* __restrict__ W1, const float* __restrict__ b1,
    const float* __restrict__ W2, const float* __restrict__ b2,
    int N)
{
    int warp = (blockIdx.x * blockDim.x + threadIdx.x) >> 5;
    if (warp >= N) return;
    int lane = threadIdx.x & 31;

    float a[4] = {0.f, 0.f, 0.f, 0.f};
    float b[4] = {0.f, 0.f, 0.f, 0.f};
    const float* frow = feat + (long long)warp * 256;
#pragma unroll
    for (int kk = 0; kk < 8; kk++) {
        int k   = lane + kk * 32;
        float f = frow[k];
#pragma unroll
        for (int j = 0; j < 4; j++) {
            a[j] = fmaf(f, __ldg(W1 + j * 256 + k), a[j]);
            b[j] = fmaf(f, __ldg(W2 + j * 256 + k), b[j]);
        }
    }
#pragma unroll
    for (int off = 16; off; off >>= 1) {
#pragma unroll
        for (int j = 0; j < 4; j++) {
            a[j] += __shfl_xor_sync(0xFFFFFFFFu, a[j], off);
            b[j] += __shfl_xor_sync(0xFFFFFFFFu, b[j], off);
        }
    }
    if (lane == 0) {
        g_h1[warp] = make_float4(a[0] + b1[0], a[1] + b1[1], a[2] + b1[2], a[3] + b1[3]);
        g_h2[warp] = make_float4(b[0] + b2[0], b[1] + b2[1], b[2] + b2[2], b[3] + b2[3]);
    }
}

// ---------------------------------------------------------------------------
// CSR build: zero, count, PARALLEL 3-pass scan, scatter
// ---------------------------------------------------------------------------
__global__ void zero_cnt_kernel(int N)
{
    int i = blockIdx.x * blockDim.x + threadIdx.x;
    if (i < N) g_cnt[i] = 0;
}

__global__ void count_kernel(const int* __restrict__ ei, int E)
{
    int e = blockIdx.x * blockDim.x + threadIdx.x;
    if (e < E) atomicAdd(&g_cnt[ei[e]], 1);
}

// Pass 1: per-1024-element block — in-block exclusive prefix -> g_off,
// block total -> g_bsum[b].  256 threads, 4 elements/thread.
__global__ __launch_bounds__(256) void scan1_kernel(int N)
{
    __shared__ int wsum[8];
    const int b = blockIdx.x;
    const int tid = threadIdx.x, lane = tid & 31, wid = tid >> 5;
    const int base = b * 1024 + tid * 4;

    int v0 = (base + 0 < N) ? g_cnt[base + 0] : 0;
    int v1 = (base + 1 < N) ? g_cnt[base + 1] : 0;
    int v2 = (base + 2 < N) ? g_cnt[base + 2] : 0;
    int v3 = (base + 3 < N) ? g_cnt[base + 3] : 0;
    int t = v0 + v1 + v2 + v3;

    int x = t;
#pragma unroll
    for (int o = 1; o < 32; o <<= 1) {
        int y = __shfl_up_sync(0xFFFFFFFFu, x, o);
        if (lane >= o) x += y;
    }
    if (lane == 31) wsum[wid] = x;
    __syncthreads();
    if (wid == 0 && lane < 8) {
        int s = wsum[lane];
#pragma unroll
        for (int o = 1; o < 8; o <<= 1) {
            int y = __shfl_up_sync(0xFFu, s, o);
            if (lane >= o) s += y;
        }
        wsum[lane] = s;
    }
    __syncthreads();

    int excl = ((wid > 0) ? wsum[wid - 1] : 0) + x - t;
    if (base + 0 < N) g_off[base + 0] = excl;
    if (base + 1 < N) g_off[base + 1] = excl + v0;
    if (base + 2 < N) g_off[base + 2] = excl + v0 + v1;
    if (base + 3 < N) g_off[base + 3] = excl + v0 + v1 + v2;
    if (tid == 0) g_bsum[b] = wsum[7];   // block total
}

// Pass 2: exclusive scan of <=64 block totals (one block, 64 threads)
__global__ void scan2_kernel(int NB)
{
    __shared__ int ws[2];
    const int tid = threadIdx.x, lane = tid & 31, wid = tid >> 5;
    int v = (tid < NB) ? g_bsum[tid] : 0;
    int x = v;
#pragma unroll
    for (int o = 1; o < 32; o <<= 1) {
        int y = __shfl_up_sync(0xFFFFFFFFu, x, o);
        if (lane >= o) x += y;
    }
    if (lane == 31) ws[wid] = x;
    __syncthreads();
    int incl = x + ((wid == 1) ? ws[0] : 0);
    if (tid < NB) g_bsum[tid] = incl - v;  // exclusive block offset
}

// Pass 3: add block offsets, init cursors, set sentinel
__global__ void scan3_kernel(int N, int E)
{
    int i = blockIdx.x * blockDim.x + threadIdx.x;
    if (i < N) {
        int o = g_off[i] + g_bsum[i >> 10];
        g_off[i] = o;
        g_cur[i] = o;
    }
    if (i == 0) g_off[N] = E;
}

__global__ void scatter_kernel(const int* __restrict__ ei, int E)
{
    int e = blockIdx.x * blockDim.x + threadIdx.x;
    if (e < E) {
        int s = ei[e];
        int d = ei[E + e];
        int pos = atomicAdd(&g_cur[s], 1);
        g_sdst[pos] = d;
    }
}

// ---------------------------------------------------------------------------
// Kernel 4: aggregate.  One warp per node, no atomics, 2-edge ILP.
// (Round-4 known-good version, unchanged.)
// ---------------------------------------------------------------------------
__global__ __launch_bounds__(256) void agg_kernel(
    const float* __restrict__ eps,
    float* __restrict__ OUT,
    int N)
{
    int node = (blockIdx.x * blockDim.x + threadIdx.x) >> 5;
    if (node >= N) return;
    int lane = threadIdx.x & 31;
    int head = lane >> 3;           // 4 heads, 8 lanes each
    int j    = lane * 4;            // feature offset (float4)

    float4 ha = g_h1[node];
    float ha_h = (head < 2) ? (head == 0 ? ha.x : ha.y)
                            : (head == 2 ? ha.z : ha.w);

    int i   = g_off[node];
    int end = g_off[node + 1];

    float4 acc0 = make_float4(0.f, 0.f, 0.f, 0.f);
    float4 acc1 = make_float4(0.f, 0.f, 0.f, 0.f);

    for (; i + 2 <= end; i += 2) {
        int d0 = __ldg(&g_sdst[i]);
        int d1 = __ldg(&g_sdst[i + 1]);
        float4 hb0 = g_h2[d0];
        float4 hb1 = g_h2[d1];
        float v0 = ha_h + ((head < 2) ? (head == 0 ? hb0.x : hb0.y)
                                      : (head == 2 ? hb0.z : hb0.w));
        float v1 = ha_h + ((head < 2) ? (head == 0 ? hb1.x : hb1.y)
                                      : (head == 2 ? hb1.z : hb1.w));
        if (v0 > 0.f) {
            float4 xv = *(const float4*)(g_x + (long long)d0 * 128 + j);
            acc0.x = fmaf(v0, xv.x, acc0.x);
            acc0.y = fmaf(v0, xv.y, acc0.y);
            acc0.z = fmaf(v0, xv.z, acc0.z);
            acc0.w = fmaf(v0, xv.w, acc0.w);
        }
        if (v1 > 0.f) {
            float4 xv = *(const float4*)(g_x + (long long)d1 * 128 + j);
            acc1.x = fmaf(v1, xv.x, acc1.x);
            acc1.y = fmaf(v1, xv.y, acc1.y);
            acc1.z = fmaf(v1, xv.z, acc1.z);
            acc1.w = fmaf(v1, xv.w, acc1.w);
        }
    }
    if (i < end) {  // tail edge
        int d0 = __ldg(&g_sdst[i]);
        float4 hb0 = g_h2[d0];
        float v0 = ha_h + ((head < 2) ? (head == 0 ? hb0.x : hb0.y)
                                      : (head == 2 ? hb0.z : hb0.w));
        if (v0 > 0.f) {
            float4 xv = *(const float4*)(g_x + (long long)d0 * 128 + j);
            acc0.x = fmaf(v0, xv.x, acc0.x);
            acc0.y = fmaf(v0, xv.y, acc0.y);
            acc0.z = fmaf(v0, xv.z, acc0.z);
            acc0.w = fmaf(v0, xv.w, acc0.w);
        }
    }

    float e0 = eps[0];
    float4 xs = *(const float4*)(g_x + (long long)node * 128 + j);
    float4 o;
    o.x = fmaf(e0, xs.x, acc0.x + acc1.x);
    o.y = fmaf(e0, xs.y, acc0.y + acc1.y);
    o.z = fmaf(e0, xs.z, acc0.z + acc1.z);
    o.w = fmaf(e0, xs.w, acc0.w + acc1.w);
    *(float4*)(OUT + (long long)node * 128 + j) = o;
}

// ---------------------------------------------------------------------------
extern "C" void kernel_launch(void* const* d_in, const int* in_sizes, int n_in,
                              void* d_out, int out_size)
{
    const float* feat  = (const float*)d_in[0];
    const int*   ei    = (const int*)d_in[1];
    const float* W_mlp = (const float*)d_in[2];
    const float* b_mlp = (const float*)d_in[3];
    const float* W1    = (const float*)d_in[4];
    const float* b1    = (const float*)d_in[5];
    const float* W2    = (const float*)d_in[6];
    const float* b2    = (const float*)d_in[7];
    const float* eps   = (const float*)d_in[8];

    const int N = in_sizes[0] / 256;
    const int E = in_sizes[1] / 2;
    float* out = (float*)d_out;

    // One-time side stream + fork/join events (host objects, no device mem)
    static cudaStream_t s_side = nullptr;
    static cudaEvent_t  ev_fork = nullptr, ev_join = nullptr;
    if (!s_side) {
        cudaStreamCreateWithFlags(&s_side, cudaStreamNonBlocking);
        cudaEventCreateWithFlags(&ev_fork, cudaEventDisableTiming);
        cudaEventCreateWithFlags(&ev_join, cudaEventDisableTiming);
    }

    const int NB = (N + 1023) / 1024;   // scan blocks (<=64 for N<=65536)

    // Fork: h projections + CSR build on side stream, hidden under the GEMM.
    cudaEventRecord(ev_fork, 0);
    cudaStreamWaitEvent(s_side, ev_fork, 0);

    h_kernel<<<(N + 7) / 8, 256, 0, s_side>>>(feat, W1, b1, W2, b2, N);
    zero_cnt_kernel<<<(N + 511) / 512, 512, 0, s_side>>>(N);
    count_kernel<<<(E + 255) / 256, 256, 0, s_side>>>(ei, E);
    scan1_kernel<<<NB, 256, 0, s_side>>>(N);
    scan2_kernel<<<1, 64, 0, s_side>>>(NB);
    scan3_kernel<<<(N + 255) / 256, 256, 0, s_side>>>(N, E);
    scatter_kernel<<<(E + 255) / 256, 256, 0, s_side>>>(ei, E);
    cudaEventRecord(ev_join, s_side);

    // Dense chain on capture (NULL) stream.
    gemm_mlp_kernel<<<(N + 127) / 128, 256>>>(feat, W_mlp, b_mlp, N);

    // Join, then atomic-free aggregation + epilogue.
    cudaStreamWaitEvent(0, ev_join, 0);
    agg_kernel<<<(N + 7) / 8, 256>>>(eps, out, N);
}

// round 14
// speedup vs baseline: 1.0667x; 1.0095x over previous
#include <cuda_runtime.h>
#include <cstdint>

// Problem sizes (fixed by the dataset; bounds for static scratch)
static constexpr int NN = 50000;
static constexpr int EE = 800000;

// Scratch (device globals: allocation-free per harness rules)
__device__ __align__(16) float g_x[(long long)NN * 128];  // mlp output [N,128]
__device__ float4 g_h1[NN];        // per-node logits, conv1 (4 heads)
__device__ float4 g_h2[NN];        // per-node logits, conv2 (4 heads)
__device__ int    g_cnt[NN];       // per-src degree
__device__ int    g_off[NN + 1];   // CSR row offsets
__device__ int    g_cur[NN];       // scatter cursors
__device__ int    g_sdst[EE];      // dst sorted by src
__device__ int    g_bsum[64];      // per-block sums for the parallel scan

// ---------------------------------------------------------------------------
// Kernel 1: X = feat @ W_mlp + b_mlp  (SGEMM, packed f32x2 FMA, 1-deep
// register prefetch so GMEM latency hides under the math of the prior tile)
// BM=128, BN=128, BK=16, 256 threads, 8x8 micro-tile per thread
// ---------------------------------------------------------------------------
__global__ __launch_bounds__(256, 2) void gemm_mlp_kernel(
    const float* __restrict__ A,     // feat [N,256]
    const float* __restrict__ B,     // W_mlp [256,128] row-major (K x N)
    const float* __restrict__ bias,  // [128]
    int N)
{
    __shared__ float As[16][128];  // transposed A tile: As[k][m]
    __shared__ float Bs[16][128];  // Bs[k][n]

    const int tid  = threadIdx.x;
    const int brow = blockIdx.x * 128;
    const int tcol = (tid & 15) * 8;   // 0..120
    const int trow = (tid >> 4) * 8;   // 0..120

    const int a_r0  = (tid * 2) >> 2;
    const int a_c0  = ((tid * 2) & 3) * 4;
    const int a_r1  = (tid * 2 + 1) >> 2;
    const int a_c1  = ((tid * 2 + 1) & 3) * 4;
    const int b_r0  = (tid * 2) >> 5;
    const int b_c0  = ((tid * 2) & 31) * 4;
    const int b_r1  = (tid * 2 + 1) >> 5;
    const int b_c1  = ((tid * 2 + 1) & 31) * 4;

    unsigned long long acc2[8][4];
#pragma unroll
    for (int i = 0; i < 8; i++)
#pragma unroll
        for (int j = 0; j < 4; j++) acc2[i][j] = 0ull;

    float4 pa0, pa1, pb0, pb1;
    {
        int gr0 = brow + a_r0, gr1 = brow + a_r1;
        pa0 = make_float4(0.f, 0.f, 0.f, 0.f);
        pa1 = make_float4(0.f, 0.f, 0.f, 0.f);
        if (gr0 < N) pa0 = *(const float4*)(A + (long long)gr0 * 256 + 0 + a_c0);
        if (gr1 < N) pa1 = *(const float4*)(A + (long long)gr1 * 256 + 0 + a_c1);
        pb0 = *(const float4*)(B + (long long)(0 + b_r0) * 128 + b_c0);
        pb1 = *(const float4*)(B + (long long)(0 + b_r1) * 128 + b_c1);
    }

    for (int k0 = 0; k0 < 256; k0 += 16) {
        As[a_c0 + 0][a_r0] = pa0.x;
        As[a_c0 + 1][a_r0] = pa0.y;
        As[a_c0 + 2][a_r0] = pa0.z;
        As[a_c0 + 3][a_r0] = pa0.w;
        As[a_c1 + 0][a_r1] = pa1.x;
        As[a_c1 + 1][a_r1] = pa1.y;
        As[a_c1 + 2][a_r1] = pa1.z;
        As[a_c1 + 3][a_r1] = pa1.w;
        *(float4*)&Bs[b_r0][b_c0] = pb0;
        *(float4*)&Bs[b_r1][b_c1] = pb1;
        __syncthreads();

        if (k0 + 16 < 256) {
            int kn = k0 + 16;
            int gr0 = brow + a_r0, gr1 = brow + a_r1;
            pa0 = make_float4(0.f, 0.f, 0.f, 0.f);
            pa1 = make_float4(0.f, 0.f, 0.f, 0.f);
            if (gr0 < N) pa0 = *(const float4*)(A + (long long)gr0 * 256 + kn + a_c0);
            if (gr1 < N) pa1 = *(const float4*)(A + (long long)gr1 * 256 + kn + a_c1);
            pb0 = *(const float4*)(B + (long long)(kn + b_r0) * 128 + b_c0);
            pb1 = *(const float4*)(B + (long long)(kn + b_r1) * 128 + b_c1);
        }

#pragma unroll
        for (int k = 0; k < 16; k++) {
            unsigned long long bn2[4];
            {
                float4 b0 = *(const float4*)&Bs[k][tcol];
                float4 b1 = *(const float4*)&Bs[k][tcol + 4];
                float2 p;
                p = make_float2(b0.x, b0.y); bn2[0] = *reinterpret_cast<unsigned long long*>(&p);
                p = make_float2(b0.z, b0.w); bn2[1] = *reinterpret_cast<unsigned long long*>(&p);
                p = make_float2(b1.x, b1.y); bn2[2] = *reinterpret_cast<unsigned long long*>(&p);
                p = make_float2(b1.z, b1.w); bn2[3] = *reinterpret_cast<unsigned long long*>(&p);
            }
            float am[8];
            {
                float4 a0 = *(const float4*)&As[k][trow];
                float4 a1 = *(const float4*)&As[k][trow + 4];
                am[0] = a0.x; am[1] = a0.y; am[2] = a0.z; am[3] = a0.w;
                am[4] = a1.x; am[5] = a1.y; am[6] = a1.z; am[7] = a1.w;
            }
#pragma unroll
            for (int i = 0; i < 8; i++) {
                unsigned long long am2;
                asm("mov.b64 %0, {%1, %1};" : "=l"(am2) : "f"(am[i]));
#pragma unroll
                for (int j = 0; j < 4; j++) {
                    asm("fma.rn.f32x2 %0, %1, %2, %3;"
                        : "=l"(acc2[i][j])
                        : "l"(am2), "l"(bn2[j]), "l"(acc2[i][j]));
                }
            }
        }
        __syncthreads();
    }

#pragma unroll
    for (int i = 0; i < 8; i++) {
        int gr = brow + trow + i;
        if (gr < N) {
#pragma unroll
            for (int j = 0; j < 2; j++) {
                float2 p0 = *reinterpret_cast<float2*>(&acc2[i][2 * j + 0]);
                float2 p1 = *reinterpret_cast<float2*>(&acc2[i][2 * j + 1]);
                float4 v;
                v.x = p0.x + bias[tcol + 4 * j + 0];
                v.y = p0.y + bias[tcol + 4 * j + 1];
                v.z = p1.x + bias[tcol + 4 * j + 2];
                v.w = p1.y + bias[tcol + 4 * j + 3];
                *(float4*)(g_x + (long long)gr * 128 + tcol + 4 * j) = v;
            }
        }
    }
}

// ---------------------------------------------------------------------------
// Kernel 2: h1 = feat @ W1^T + b1, h2 = feat @ W2^T + b2   (one warp / node)
// ---------------------------------------------------------------------------
__global__ __launch_bounds__(256) void h_kernel(
    const float* __restrict__ feat,
    const float* __restrict__ W1, const float* __restrict__ b1,
    const float* __restrict__ W2, const float* __restrict__ b2,
    int N)
{
    int warp = (blockIdx.x * blockDim.x + threadIdx.x) >> 5;
    if (warp >= N) return;
    int lane = threadIdx.x & 31;

    float a[4] = {0.f, 0.f, 0.f, 0.f};
    float b[4] = {0.f, 0.f, 0.f, 0.f};
    const float* frow = feat + (long long)warp * 256;
#pragma unroll
    for (int kk = 0; kk < 8; kk++) {
        int k   = lane + kk * 32;
        float f = frow[k];
#pragma unroll
        for (int j = 0; j < 4; j++) {
            a[j] = fmaf(f, __ldg(W1 + j * 256 + k), a[j]);
            b[j] = fmaf(f, __ldg(W2 + j * 256 + k), b[j]);
        }
    }
#pragma unroll
    for (int off = 16; off; off >>= 1) {
#pragma unroll
        for (int j = 0; j < 4; j++) {
            a[j] += __shfl_xor_sync(0xFFFFFFFFu, a[j], off);
            b[j] += __shfl_xor_sync(0xFFFFFFFFu, b[j], off);
        }
    }
    if (lane == 0) {
        g_h1[warp] = make_float4(a[0] + b1[0], a[1] + b1[1], a[2] + b1[2], a[3] + b1[3]);
        g_h2[warp] = make_float4(b[0] + b2[0], b[1] + b2[1], b[2] + b2[2], b[3] + b2[3]);
    }
}

// ---------------------------------------------------------------------------
// CSR build: zero, count, PARALLEL 3-pass scan, scatter
// ---------------------------------------------------------------------------
__global__ void zero_cnt_kernel(int N)
{
    int i = blockIdx.x * blockDim.x + threadIdx.x;
    if (i < N) g_cnt[i] = 0;
}

__global__ void count_kernel(const int* __restrict__ ei, int E)
{
    int e = blockIdx.x * blockDim.x + threadIdx.x;
    if (e < E) atomicAdd(&g_cnt[ei[e]], 1);
}

// Pass 1: per-1024-element block — in-block exclusive prefix -> g_off,
// block total -> g_bsum[b].  256 threads, 4 elements/thread.
__global__ __launch_bounds__(256) void scan1_kernel(int N)
{
    __shared__ int wsum[8];
    const int b = blockIdx.x;
    const int tid = threadIdx.x, lane = tid & 31, wid = tid >> 5;
    const int base = b * 1024 + tid * 4;

    int v0 = (base + 0 < N) ? g_cnt[base + 0] : 0;
    int v1 = (base + 1 < N) ? g_cnt[base + 1] : 0;
    int v2 = (base + 2 < N) ? g_cnt[base + 2] : 0;
    int v3 = (base + 3 < N) ? g_cnt[base + 3] : 0;
    int t = v0 + v1 + v2 + v3;

    int x = t;
#pragma unroll
    for (int o = 1; o < 32; o <<= 1) {
        int y = __shfl_up_sync(0xFFFFFFFFu, x, o);
        if (lane >= o) x += y;
    }
    if (lane == 31) wsum[wid] = x;
    __syncthreads();
    if (wid == 0 && lane < 8) {
        int s = wsum[lane];
#pragma unroll
        for (int o = 1; o < 8; o <<= 1) {
            int y = __shfl_up_sync(0xFFu, s, o);
            if (lane >= o) s += y;
        }
        wsum[lane] = s;
    }
    __syncthreads();

    int excl = ((wid > 0) ? wsum[wid - 1] : 0) + x - t;
    if (base + 0 < N) g_off[base + 0] = excl;
    if (base + 1 < N) g_off[base + 1] = excl + v0;
    if (base + 2 < N) g_off[base + 2] = excl + v0 + v1;
    if (base + 3 < N) g_off[base + 3] = excl + v0 + v1 + v2;
    if (tid == 0) g_bsum[b] = wsum[7];   // block total
}

// Pass 2: exclusive scan of <=64 block totals (one block, 64 threads)
__global__ void scan2_kernel(int NB)
{
    __shared__ int ws[2];
    const int tid = threadIdx.x, lane = tid & 31, wid = tid >> 5;
    int v = (tid < NB) ? g_bsum[tid] : 0;
    int x = v;
#pragma unroll
    for (int o = 1; o < 32; o <<= 1) {
        int y = __shfl_up_sync(0xFFFFFFFFu, x, o);
        if (lane >= o) x += y;
    }
    if (lane == 31) ws[wid] = x;
    __syncthreads();
    int incl = x + ((wid == 1) ? ws[0] : 0);
    if (tid < NB) g_bsum[tid] = incl - v;  // exclusive block offset
}

// Pass 3: add block offsets, init cursors, set sentinel
__global__ void scan3_kernel(int N, int E)
{
    int i = blockIdx.x * blockDim.x + threadIdx.x;
    if (i < N) {
        int o = g_off[i] + g_bsum[i >> 10];
        g_off[i] = o;
        g_cur[i] = o;
    }
    if (i == 0) g_off[N] = E;
}

__global__ void scatter_kernel(const int* __restrict__ ei, int E)
{
    int e = blockIdx.x * blockDim.x + threadIdx.x;
    if (e < E) {
        int s = ei[e];
        int d = ei[E + e];
        int pos = atomicAdd(&g_cur[s], 1);
        g_sdst[pos] = d;
    }
}

// ---------------------------------------------------------------------------
// Kernel 4: aggregate.  One warp per node, no atomics, 2-edge ILP.
// (Round-4 known-good version, unchanged.)
// ---------------------------------------------------------------------------
__global__ __launch_bounds__(256) void agg_kernel(
    const float* __restrict__ eps,
    float* __restrict__ OUT,
    int N)
{
    int node = (blockIdx.x * blockDim.x + threadIdx.x) >> 5;
    if (node >= N) return;
    int lane = threadIdx.x & 31;
    int head = lane >> 3;           // 4 heads, 8 lanes each
    int j    = lane * 4;            // feature offset (float4)

    float4 ha = g_h1[node];
    float ha_h = (head < 2) ? (head == 0 ? ha.x : ha.y)
                            : (head == 2 ? ha.z : ha.w);

    int i   = g_off[node];
    int end = g_off[node + 1];

    float4 acc0 = make_float4(0.f, 0.f, 0.f, 0.f);
    float4 acc1 = make_float4(0.f, 0.f, 0.f, 0.f);

    for (; i + 2 <= end; i += 2) {
        int d0 = __ldg(&g_sdst[i]);
        int d1 = __ldg(&g_sdst[i + 1]);
        float4 hb0 = g_h2[d0];
        float4 hb1 = g_h2[d1];
        float v0 = ha_h + ((head < 2) ? (head == 0 ? hb0.x : hb0.y)
                                      : (head == 2 ? hb0.z : hb0.w));
        float v1 = ha_h + ((head < 2) ? (head == 0 ? hb1.x : hb1.y)
                                      : (head == 2 ? hb1.z : hb1.w));
        if (v0 > 0.f) {
            float4 xv = *(const float4*)(g_x + (long long)d0 * 128 + j);
            acc0.x = fmaf(v0, xv.x, acc0.x);
            acc0.y = fmaf(v0, xv.y, acc0.y);
            acc0.z = fmaf(v0, xv.z, acc0.z);
            acc0.w = fmaf(v0, xv.w, acc0.w);
        }
        if (v1 > 0.f) {
            float4 xv = *(const float4*)(g_x + (long long)d1 * 128 + j);
            acc1.x = fmaf(v1, xv.x, acc1.x);
            acc1.y = fmaf(v1, xv.y, acc1.y);
            acc1.z = fmaf(v1, xv.z, acc1.z);
            acc1.w = fmaf(v1, xv.w, acc1.w);
        }
    }
    if (i < end) {  // tail edge
        int d0 = __ldg(&g_sdst[i]);
        float4 hb0 = g_h2[d0];
        float v0 = ha_h + ((head < 2) ? (head == 0 ? hb0.x : hb0.y)
                                      : (head == 2 ? hb0.z : hb0.w));
        if (v0 > 0.f) {
            float4 xv = *(const float4*)(g_x + (long long)d0 * 128 + j);
            acc0.x = fmaf(v0, xv.x, acc0.x);
            acc0.y = fmaf(v0, xv.y, acc0.y);
            acc0.z = fmaf(v0, xv.z, acc0.z);
            acc0.w = fmaf(v0, xv.w, acc0.w);
        }
    }

    float e0 = eps[0];
    float4 xs = *(const float4*)(g_x + (long long)node * 128 + j);
    float4 o;
    o.x = fmaf(e0, xs.x, acc0.x + acc1.x);
    o.y = fmaf(e0, xs.y, acc0.y + acc1.y);
    o.z = fmaf(e0, xs.z, acc0.z + acc1.z);
    o.w = fmaf(e0, xs.w, acc0.w + acc1.w);
    *(float4*)(OUT + (long long)node * 128 + j) = o;
}

// ---------------------------------------------------------------------------
extern "C" void kernel_launch(void* const* d_in, const int* in_sizes, int n_in,
                              void* d_out, int out_size)
{
    const float* feat  = (const float*)d_in[0];
    const int*   ei    = (const int*)d_in[1];
    const float* W_mlp = (const float*)d_in[2];
    const float* b_mlp = (const float*)d_in[3];
    const float* W1    = (const float*)d_in[4];
    const float* b1    = (const float*)d_in[5];
    const float* W2    = (const float*)d_in[6];
    const float* b2    = (const float*)d_in[7];
    const float* eps   = (const float*)d_in[8];

    const int N = in_sizes[0] / 256;
    const int E = in_sizes[1] / 2;
    float* out = (float*)d_out;

    // One-time side stream + fork/join events (host objects, no device mem)
    static cudaStream_t s_side = nullptr;
    static cudaEvent_t  ev_fork = nullptr, ev_join = nullptr;
    if (!s_side) {
        cudaStreamCreateWithFlags(&s_side, cudaStreamNonBlocking);
        cudaEventCreateWithFlags(&ev_fork, cudaEventDisableTiming);
        cudaEventCreateWithFlags(&ev_join, cudaEventDisableTiming);
    }

    const int NB = (N + 1023) / 1024;   // scan blocks (<=64 for N<=65536)

    // Fork: h projections + CSR build on side stream, hidden under the GEMM.
    cudaEventRecord(ev_fork, 0);
    cudaStreamWaitEvent(s_side, ev_fork, 0);

    h_kernel<<<(N + 7) / 8, 256, 0, s_side>>>(feat, W1, b1, W2, b2, N);
    zero_cnt_kernel<<<(N + 511) / 512, 512, 0, s_side>>>(N);
    count_kernel<<<(E + 255) / 256, 256, 0, s_side>>>(ei, E);
    scan1_kernel<<<NB, 256, 0, s_side>>>(N);
    scan2_kernel<<<1, 64, 0, s_side>>>(NB);
    scan3_kernel<<<(N + 255) / 256, 256, 0, s_side>>>(N, E);
    scatter_kernel<<<(E + 255) / 256, 256, 0, s_side>>>(ei, E);
    cudaEventRecord(ev_join, s_side);

    // Dense chain on capture (NULL) stream.
    gemm_mlp_kernel<<<(N + 127) / 128, 256>>>(feat, W_mlp, b_mlp, N);

    // Join, then atomic-free aggregation + epilogue.
    cudaStreamWaitEvent(0, ev_join, 0);
    agg_kernel<<<(N + 7) / 8, 256>>>(eps, out, N);
}

// round 15
// speedup vs baseline: 1.0745x; 1.0074x over previous
#include <cuda_runtime.h>
#include <cstdint>

// Problem sizes (fixed by the dataset; bounds for static scratch)
static constexpr int NN = 50000;
static constexpr int EE = 800000;

// Scratch (device globals: allocation-free per harness rules)
__device__ __align__(16) float g_x[(long long)NN * 128];  // mlp output [N,128]
__device__ float4 g_h1[NN];        // per-node logits, conv1 (4 heads)
__device__ float4 g_h2[NN];        // per-node logits, conv2 (4 heads)
__device__ int    g_cnt[NN];       // per-src degree
__device__ int    g_off[NN + 1];   // CSR row offsets
__device__ int    g_cur[NN];       // scatter cursors
__device__ int    g_sdst[EE];      // dst sorted by src
__device__ int    g_bsum[64];      // per-block sums for the parallel scan

// ---------------------------------------------------------------------------
// Half-GEMM: g_x[:, colofs..colofs+63] = feat @ W_mlp[:, colofs..+63] + bias
// BM=128, BN=64, BK=16, 256 threads, 8x4 micro-tile, packed f32x2 FMA.
// (ALU-bound: splitting by N costs no extra FLOPs, enables GEMM/agg overlap.)
// ---------------------------------------------------------------------------
__global__ __launch_bounds__(256) void gemm_half_kernel(
    const float* __restrict__ A,     // feat [N,256]
    const float* __restrict__ B,     // W_mlp [256,128] row-major (K x N)
    const float* __restrict__ bias,  // [128]
    int N, int colofs)
{
    __shared__ float As[16][128];  // transposed A tile: As[k][m]
    __shared__ float Bs[16][64];   // Bs[k][n]

    const int tid  = threadIdx.x;
    const int brow = blockIdx.x * 128;
    const int tcol = (tid & 15) * 4;   // 0..60
    const int trow = (tid >> 4) * 8;   // 0..120

    unsigned long long acc2[8][2];
#pragma unroll
    for (int i = 0; i < 8; i++) { acc2[i][0] = 0ull; acc2[i][1] = 0ull; }

    for (int k0 = 0; k0 < 256; k0 += 16) {
        // A tile: 128 rows x 16 k, transposed.  2 float4 / thread.
#pragma unroll
        for (int i = 0; i < 2; i++) {
            int idx = tid * 2 + i;          // 0..511
            int r   = idx >> 2;             // 0..127
            int c4  = (idx & 3) * 4;        // 0,4,8,12
            int gr  = brow + r;
            float4 v = make_float4(0.f, 0.f, 0.f, 0.f);
            if (gr < N) v = *(const float4*)(A + (long long)gr * 256 + k0 + c4);
            As[c4 + 0][r] = v.x;
            As[c4 + 1][r] = v.y;
            As[c4 + 2][r] = v.z;
            As[c4 + 3][r] = v.w;
        }
        // B tile: 16 k x 64 n.  1 float4 / thread.
        {
            int r  = tid >> 4;              // 0..15
            int c4 = (tid & 15) * 4;        // 0..60
            *(float4*)&Bs[r][c4] =
                *(const float4*)(B + (long long)(k0 + r) * 128 + colofs + c4);
        }
        __syncthreads();

#pragma unroll
        for (int k = 0; k < 16; k++) {
            unsigned long long bn2[2];
            {
                float4 b0 = *(const float4*)&Bs[k][tcol];
                float2 p;
                p = make_float2(b0.x, b0.y); bn2[0] = *reinterpret_cast<unsigned long long*>(&p);
                p = make_float2(b0.z, b0.w); bn2[1] = *reinterpret_cast<unsigned long long*>(&p);
            }
            float am[8];
            {
                float4 a0 = *(const float4*)&As[k][trow];
                float4 a1 = *(const float4*)&As[k][trow + 4];
                am[0] = a0.x; am[1] = a0.y; am[2] = a0.z; am[3] = a0.w;
                am[4] = a1.x; am[5] = a1.y; am[6] = a1.z; am[7] = a1.w;
            }
#pragma unroll
            for (int i = 0; i < 8; i++) {
                unsigned long long am2;
                asm("mov.b64 %0, {%1, %1};" : "=l"(am2) : "f"(am[i]));
                asm("fma.rn.f32x2 %0, %1, %2, %3;"
                    : "=l"(acc2[i][0]) : "l"(am2), "l"(bn2[0]), "l"(acc2[i][0]));
                asm("fma.rn.f32x2 %0, %1, %2, %3;"
                    : "=l"(acc2[i][1]) : "l"(am2), "l"(bn2[1]), "l"(acc2[i][1]));
            }
        }
        __syncthreads();
    }

#pragma unroll
    for (int i = 0; i < 8; i++) {
        int gr = brow + trow + i;
        if (gr < N) {
            float2 p0 = *reinterpret_cast<float2*>(&acc2[i][0]);
            float2 p1 = *reinterpret_cast<float2*>(&acc2[i][1]);
            float4 v;
            v.x = p0.x + __ldg(bias + colofs + tcol + 0);
            v.y = p0.y + __ldg(bias + colofs + tcol + 1);
            v.z = p1.x + __ldg(bias + colofs + tcol + 2);
            v.w = p1.y + __ldg(bias + colofs + tcol + 3);
            *(float4*)(g_x + (long long)gr * 128 + colofs + tcol) = v;
        }
    }
}

// ---------------------------------------------------------------------------
// Kernel 2: h1 = feat @ W1^T + b1, h2 = feat @ W2^T + b2   (one warp / node)
// ---------------------------------------------------------------------------
__global__ __launch_bounds__(256) void h_kernel(
    const float* __restrict__ feat,
    const float* __restrict__ W1, const float* __restrict__ b1,
    const float* __restrict__ W2, const float* __restrict__ b2,
    int N)
{
    int warp = (blockIdx.x * blockDim.x + threadIdx.x) >> 5;
    if (warp >= N) return;
    int lane = threadIdx.x & 31;

    float a[4] = {0.f, 0.f, 0.f, 0.f};
    float b[4] = {0.f, 0.f, 0.f, 0.f};
    const float* frow = feat + (long long)warp * 256;
#pragma unroll
    for (int kk = 0; kk < 8; kk++) {
        int k   = lane + kk * 32;
        float f = frow[k];
#pragma unroll
        for (int j = 0; j < 4; j++) {
            a[j] = fmaf(f, __ldg(W1 + j * 256 + k), a[j]);
            b[j] = fmaf(f, __ldg(W2 + j * 256 + k), b[j]);
        }
    }
#pragma unroll
    for (int off = 16; off; off >>= 1) {
#pragma unroll
        for (int j = 0; j < 4; j++) {
            a[j] += __shfl_xor_sync(0xFFFFFFFFu, a[j], off);
            b[j] += __shfl_xor_sync(0xFFFFFFFFu, b[j], off);
        }
    }
    if (lane == 0) {
        g_h1[warp] = make_float4(a[0] + b1[0], a[1] + b1[1], a[2] + b1[2], a[3] + b1[3]);
        g_h2[warp] = make_float4(b[0] + b2[0], b[1] + b2[1], b[2] + b2[2], b[3] + b2[3]);
    }
}

// ---------------------------------------------------------------------------
// CSR build: zero, count, PARALLEL 3-pass scan, scatter
// ---------------------------------------------------------------------------
__global__ void zero_cnt_kernel(int N)
{
    int i = blockIdx.x * blockDim.x + threadIdx.x;
    if (i < N) g_cnt[i] = 0;
}

__global__ void count_kernel(const int* __restrict__ ei, int E)
{
    int e = blockIdx.x * blockDim.x + threadIdx.x;
    if (e < E) atomicAdd(&g_cnt[ei[e]], 1);
}

// Pass 1: per-1024-element block — in-block exclusive prefix -> g_off,
// block total -> g_bsum[b].  256 threads, 4 elements/thread.
__global__ __launch_bounds__(256) void scan1_kernel(int N)
{
    __shared__ int wsum[8];
    const int b = blockIdx.x;
    const int tid = threadIdx.x, lane = tid & 31, wid = tid >> 5;
    const int base = b * 1024 + tid * 4;

    int v0 = (base + 0 < N) ? g_cnt[base + 0] : 0;
    int v1 = (base + 1 < N) ? g_cnt[base + 1] : 0;
    int v2 = (base + 2 < N) ? g_cnt[base + 2] : 0;
    int v3 = (base + 3 < N) ? g_cnt[base + 3] : 0;
    int t = v0 + v1 + v2 + v3;

    int x = t;
#pragma unroll
    for (int o = 1; o < 32; o <<= 1) {
        int y = __shfl_up_sync(0xFFFFFFFFu, x, o);
        if (lane >= o) x += y;
    }
    if (lane == 31) wsum[wid] = x;
    __syncthreads();
    if (wid == 0 && lane < 8) {
        int s = wsum[lane];
#pragma unroll
        for (int o = 1; o < 8; o <<= 1) {
            int y = __shfl_up_sync(0xFFu, s, o);
            if (lane >= o) s += y;
        }
        wsum[lane] = s;
    }
    __syncthreads();

    int excl = ((wid > 0) ? wsum[wid - 1] : 0) + x - t;
    if (base + 0 < N) g_off[base + 0] = excl;
    if (base + 1 < N) g_off[base + 1] = excl + v0;
    if (base + 2 < N) g_off[base + 2] = excl + v0 + v1;
    if (base + 3 < N) g_off[base + 3] = excl + v0 + v1 + v2;
    if (tid == 0) g_bsum[b] = wsum[7];   // block total
}

// Pass 2: exclusive scan of <=64 block totals (one block, 64 threads)
__global__ void scan2_kernel(int NB)
{
    __shared__ int ws[2];
    const int tid = threadIdx.x, lane = tid & 31, wid = tid >> 5;
    int v = (tid < NB) ? g_bsum[tid] : 0;
    int x = v;
#pragma unroll
    for (int o = 1; o < 32; o <<= 1) {
        int y = __shfl_up_sync(0xFFFFFFFFu, x, o);
        if (lane >= o) x += y;
    }
    if (lane == 31) ws[wid] = x;
    __syncthreads();
    int incl = x + ((wid == 1) ? ws[0] : 0);
    if (tid < NB) g_bsum[tid] = incl - v;  // exclusive block offset
}

// Pass 3: add block offsets, init cursors, set sentinel
__global__ void scan3_kernel(int N, int E)
{
    int i = blockIdx.x * blockDim.x + threadIdx.x;
    if (i < N) {
        int o = g_off[i] + g_bsum[i >> 10];
        g_off[i] = o;
        g_cur[i] = o;
    }
    if (i == 0) g_off[N] = E;
}

__global__ void scatter_kernel(const int* __restrict__ ei, int E)
{
    int e = blockIdx.x * blockDim.x + threadIdx.x;
    if (e < E) {
        int s = ei[e];
        int d = ei[E + e];
        int pos = atomicAdd(&g_cur[s], 1);
        g_sdst[pos] = d;
    }
}

// ---------------------------------------------------------------------------
// Half-aggregate: columns [colofs, colofs+64).  One warp per node, float2/lane.
//   out[n][j] = sum_{e: src=n} relu(h1[n][h]+h2[dst][h]) * x[dst][j]
//               + eps * x[n][j],   j = colofs + lane*2, h = j/32
// ---------------------------------------------------------------------------
__device__ __forceinline__ float head_sel(const float4 h, int head) {
    return (head & 2) ? ((head & 1) ? h.w : h.z)
                      : ((head & 1) ? h.y : h.x);
}

__global__ __launch_bounds__(256) void agg_half_kernel(
    const float* __restrict__ eps,
    float* __restrict__ OUT,
    int N, int colofs)
{
    int node = (blockIdx.x * blockDim.x + threadIdx.x) >> 5;
    if (node >= N) return;
    int lane = threadIdx.x & 31;
    int j    = colofs + lane * 2;   // feature offset (float2)
    int head = j >> 5;

    float ha_h = head_sel(g_h1[node], head);

    int i   = g_off[node];
    int end = g_off[node + 1];

    float2 acc0 = make_float2(0.f, 0.f);
    float2 acc1 = make_float2(0.f, 0.f);

    for (; i + 2 <= end; i += 2) {
        int d0 = __ldg(&g_sdst[i]);
        int d1 = __ldg(&g_sdst[i + 1]);
        float v0 = ha_h + head_sel(g_h2[d0], head);
        float v1 = ha_h + head_sel(g_h2[d1], head);
        if (v0 > 0.f) {
            float2 xv = *(const float2*)(g_x + (long long)d0 * 128 + j);
            acc0.x = fmaf(v0, xv.x, acc0.x);
            acc0.y = fmaf(v0, xv.y, acc0.y);
        }
        if (v1 > 0.f) {
            float2 xv = *(const float2*)(g_x + (long long)d1 * 128 + j);
            acc1.x = fmaf(v1, xv.x, acc1.x);
            acc1.y = fmaf(v1, xv.y, acc1.y);
        }
    }
    if (i < end) {  // tail edge
        int d0 = __ldg(&g_sdst[i]);
        float v0 = ha_h + head_sel(g_h2[d0], head);
        if (v0 > 0.f) {
            float2 xv = *(const float2*)(g_x + (long long)d0 * 128 + j);
            acc0.x = fmaf(v0, xv.x, acc0.x);
            acc0.y = fmaf(v0, xv.y, acc0.y);
        }
    }

    float e0 = eps[0];
    float2 xs = *(const float2*)(g_x + (long long)node * 128 + j);
    float2 o;
    o.x = fmaf(e0, xs.x, acc0.x + acc1.x);
    o.y = fmaf(e0, xs.y, acc0.y + acc1.y);
    *(float2*)(OUT + (long long)node * 128 + j) = o;
}

// ---------------------------------------------------------------------------
extern "C" void kernel_launch(void* const* d_in, const int* in_sizes, int n_in,
                              void* d_out, int out_size)
{
    const float* feat  = (const float*)d_in[0];
    const int*   ei    = (const int*)d_in[1];
    const float* W_mlp = (const float*)d_in[2];
    const float* b_mlp = (const float*)d_in[3];
    const float* W1    = (const float*)d_in[4];
    const float* b1    = (const float*)d_in[5];
    const float* W2    = (const float*)d_in[6];
    const float* b2    = (const float*)d_in[7];
    const float* eps   = (const float*)d_in[8];

    const int N = in_sizes[0] / 256;
    const int E = in_sizes[1] / 2;
    float* out = (float*)d_out;

    // One-time streams + events (host objects, no device mem)
    static cudaStream_t s_side = nullptr, s_h = nullptr, s_agg = nullptr;
    static cudaEvent_t  ev_fork = nullptr, ev_csr = nullptr, ev_h = nullptr,
                        ev_g0 = nullptr, ev_a0 = nullptr;
    if (!s_side) {
        cudaStreamCreateWithFlags(&s_side, cudaStreamNonBlocking);
        cudaStreamCreateWithFlags(&s_h,    cudaStreamNonBlocking);
        cudaStreamCreateWithFlags(&s_agg,  cudaStreamNonBlocking);
        cudaEventCreateWithFlags(&ev_fork, cudaEventDisableTiming);
        cudaEventCreateWithFlags(&ev_csr,  cudaEventDisableTiming);
        cudaEventCreateWithFlags(&ev_h,    cudaEventDisableTiming);
        cudaEventCreateWithFlags(&ev_g0,   cudaEventDisableTiming);
        cudaEventCreateWithFlags(&ev_a0,   cudaEventDisableTiming);
    }

    const int NB = (N + 1023) / 1024;   // scan blocks (<=64 for N<=65536)

    // Fork
    cudaEventRecord(ev_fork, 0);
    cudaStreamWaitEvent(s_side, ev_fork, 0);
    cudaStreamWaitEvent(s_h,    ev_fork, 0);
    cudaStreamWaitEvent(s_agg,  ev_fork, 0);

    // s_h: attention-logit projections (independent of CSR build).
    h_kernel<<<(N + 7) / 8, 256, 0, s_h>>>(feat, W1, b1, W2, b2, N);
    cudaEventRecord(ev_h, s_h);

    // s_side: CSR build with parallel scan (~40us).
    zero_cnt_kernel<<<(N + 511) / 512, 512, 0, s_side>>>(N);
    count_kernel<<<(E + 255) / 256, 256, 0, s_side>>>(ei, E);
    scan1_kernel<<<NB, 256, 0, s_side>>>(N);
    scan2_kernel<<<1, 64, 0, s_side>>>(NB);
    scan3_kernel<<<(N + 255) / 256, 256, 0, s_side>>>(N, E);
    scatter_kernel<<<(E + 255) / 256, 256, 0, s_side>>>(ei, E);
    cudaEventRecord(ev_csr, s_side);

    // Main: half-GEMM 0 (cols 0-63) then half-GEMM 1 (cols 64-127).
    gemm_half_kernel<<<(N + 127) / 128, 256>>>(feat, W_mlp, b_mlp, N, 0);
    cudaEventRecord(ev_g0, 0);
    gemm_half_kernel<<<(N + 127) / 128, 256>>>(feat, W_mlp, b_mlp, N, 64);

    // s_agg: agg half 0 — starts after g0 + CSR + h, CO-RUNS with half-GEMM 1
    // (agg is memory-bound, GEMM is ALU-bound: complementary pipes).
    cudaStreamWaitEvent(s_agg, ev_g0,  0);
    cudaStreamWaitEvent(s_agg, ev_csr, 0);
    cudaStreamWaitEvent(s_agg, ev_h,   0);
    agg_half_kernel<<<(N + 7) / 8, 256, 0, s_agg>>>(eps, out, N, 0);
    cudaEventRecord(ev_a0, s_agg);

    // Main: agg half 1 after g1 (program order) + CSR + h; co-runs with a0 tail.
    cudaStreamWaitEvent(0, ev_csr, 0);
    cudaStreamWaitEvent(0, ev_h,   0);
    agg_half_kernel<<<(N + 7) / 8, 256>>>(eps, out, N, 64);

    // Join agg half 0 into the output dependency chain.
    cudaStreamWaitEvent(0, ev_a0, 0);
}

// round 16
// speedup vs baseline: 1.3914x; 1.2949x over previous
#include <cuda_runtime.h>
#include <cuda_bf16.h>
#include <cstdint>

// Problem sizes (fixed by the dataset; bounds for static scratch)
static constexpr int NN = 50000;
static constexpr int EE = 800000;

// Scratch (device globals: allocation-free per harness rules)
__device__ __align__(16) float g_x[(long long)NN * 128];  // mlp output [N,128]
__device__ float4 g_h1[NN];        // per-node logits, conv1 (4 heads)
__device__ float4 g_h2[NN];        // per-node logits, conv2 (4 heads)
__device__ int    g_cnt[NN];       // per-src degree
__device__ int    g_off[NN + 1];   // CSR row offsets
__device__ int    g_cur[NN];       // scatter cursors
__device__ int    g_sdst[EE];      // dst sorted by src
__device__ int    g_bsum[64];      // per-block sums for the parallel scan

// ===========================================================================
// Kernel 1: X = feat @ W_mlp + b_mlp via warp-level mma.sync (HMMA, bf16-split)
//   D = Ah*Bh + Ah*Bl + Al*Bh  (hi/lo bf16 decomposition ~ fp32 accuracy)
// BM=128, BN=128, BK=64 staged; 8 warps (2M x 4N), warp tile 64x32.
// ===========================================================================
__device__ __forceinline__ unsigned smem_u32(const void* p) {
    unsigned a;
    asm("{ .reg .u64 t; cvta.to.shared.u64 t, %1; cvt.u32.u64 %0, t; }"
        : "=r"(a) : "l"(p));
    return a;
}

__device__ __forceinline__ void ldsm4(unsigned* r, unsigned addr) {
    asm volatile("ldmatrix.sync.aligned.m8n8.x4.shared.b16 {%0,%1,%2,%3}, [%4];"
                 : "=r"(r[0]), "=r"(r[1]), "=r"(r[2]), "=r"(r[3]) : "r"(addr));
}
__device__ __forceinline__ void ldsm2(unsigned* r, unsigned addr) {
    asm volatile("ldmatrix.sync.aligned.m8n8.x2.shared.b16 {%0,%1}, [%2];"
                 : "=r"(r[0]), "=r"(r[1]) : "r"(addr));
}
__device__ __forceinline__ void mma_bf16(float* d, const unsigned* a, const unsigned* b) {
    asm volatile(
        "mma.sync.aligned.m16n8k16.row.col.f32.bf16.bf16.f32 "
        "{%0,%1,%2,%3}, {%4,%5,%6,%7}, {%8,%9}, {%0,%1,%2,%3};"
        : "+f"(d[0]), "+f"(d[1]), "+f"(d[2]), "+f"(d[3])
        : "r"(a[0]), "r"(a[1]), "r"(a[2]), "r"(a[3]), "r"(b[0]), "r"(b[1]));
}

static constexpr int PITCH  = 144;             // bytes per bf16 smem row (64+8 elems)
static constexpr int SM_AH  = 0;
static constexpr int SM_AL  = 128 * PITCH;     // 18432
static constexpr int SM_BH  = 2 * 128 * PITCH; // 36864
static constexpr int SM_BL  = 3 * 128 * PITCH; // 55296
static constexpr int SM_GEMM = 4 * 128 * PITCH; // 73728 bytes dynamic smem

__global__ __launch_bounds__(256) void gemm_mma_kernel(
    const float* __restrict__ A,     // feat [N,256]
    const float* __restrict__ B,     // W_mlp [256,128]
    const float* __restrict__ bias,  // [128]
    int N)
{
    extern __shared__ __align__(16) char smem[];
    const unsigned sb = smem_u32(smem);
    const int tid  = threadIdx.x;
    const int lane = tid & 31;
    const int wid  = tid >> 5;
    const int wm   = wid >> 2;       // 0..1 (M)
    const int wn   = wid & 3;        // 0..3 (N)
    const int brow = blockIdx.x * 128;

    float acc[4][4][4];
#pragma unroll
    for (int mf = 0; mf < 4; mf++)
#pragma unroll
        for (int nf = 0; nf < 4; nf++)
#pragma unroll
            for (int q = 0; q < 4; q++) acc[mf][nf][q] = 0.f;

    // ldmatrix lane addressing (fixed per lane)
    const int a_row = lane & 15;                 // rows 0..15 within 16-row frag
    const int a_k8  = (lane & 16) ? 8 : 0;       // k halves
    const int b_row = lane & 7;
    const int b_k8  = (lane & 8) ? 8 : 0;

    for (int ko = 0; ko < 256; ko += 64) {
        // ---- stage A: 128 rows x 64 k, fp32 -> (hi, lo) bf16, padded rows
#pragma unroll
        for (int it = 0; it < 16; it++) {
            int f   = tid + it * 256;       // 0..4095 float2 slots
            int row = f >> 5;               // one warp covers one row
            int kc  = (f & 31) * 2;
            int gr  = brow + row;
            float2 v = make_float2(0.f, 0.f);
            if (gr < N) v = *(const float2*)(A + (long long)gr * 256 + ko + kc);
            __nv_bfloat16 h0 = __float2bfloat16(v.x);
            __nv_bfloat16 h1 = __float2bfloat16(v.y);
            __nv_bfloat16 l0 = __float2bfloat16(v.x - __bfloat162float(h0));
            __nv_bfloat16 l1 = __float2bfloat16(v.y - __bfloat162float(h1));
            unsigned wh = (unsigned)__bfloat16_as_ushort(h0)
                        | ((unsigned)__bfloat16_as_ushort(h1) << 16);
            unsigned wl = (unsigned)__bfloat16_as_ushort(l0)
                        | ((unsigned)__bfloat16_as_ushort(l1) << 16);
            *(unsigned*)(smem + SM_AH + row * PITCH + kc * 2) = wh;
            *(unsigned*)(smem + SM_AL + row * PITCH + kc * 2) = wl;
        }
        // ---- stage B: Bt[n][k] bf16 hi/lo; thread packs 2 consecutive k
#pragma unroll
        for (int it = 0; it < 16; it++) {
            int g  = tid + it * 256;        // 0..4095 words
            int n  = g & 127;
            int kw = g >> 7;                // 0..31 (k-pair)
            float b0 = __ldg(B + (long long)(ko + 2 * kw + 0) * 128 + n);
            float b1 = __ldg(B + (long long)(ko + 2 * kw + 1) * 128 + n);
            __nv_bfloat16 h0 = __float2bfloat16(b0);
            __nv_bfloat16 h1 = __float2bfloat16(b1);
            __nv_bfloat16 l0 = __float2bfloat16(b0 - __bfloat162float(h0));
            __nv_bfloat16 l1 = __float2bfloat16(b1 - __bfloat162float(h1));
            unsigned wh = (unsigned)__bfloat16_as_ushort(h0)
                        | ((unsigned)__bfloat16_as_ushort(h1) << 16);
            unsigned wl = (unsigned)__bfloat16_as_ushort(l0)
                        | ((unsigned)__bfloat16_as_ushort(l1) << 16);
            *(unsigned*)(smem + SM_BH + n * PITCH + kw * 4) = wh;
            *(unsigned*)(smem + SM_BL + n * PITCH + kw * 4) = wl;
        }
        __syncthreads();

        // ---- MMA over 4 k16 sub-chunks
#pragma unroll
        for (int ks = 0; ks < 64; ks += 16) {
            unsigned ah[4][4], al[4][4], bh[4][2], bl[4][2];
#pragma unroll
            for (int mf = 0; mf < 4; mf++) {
                int r = wm * 64 + mf * 16 + a_row;
                unsigned off = (unsigned)(r * PITCH + (ks + a_k8) * 2);
                ldsm4(ah[mf], sb + SM_AH + off);
                ldsm4(al[mf], sb + SM_AL + off);
            }
#pragma unroll
            for (int nf = 0; nf < 4; nf++) {
                int r = wn * 32 + nf * 8 + b_row;
                unsigned off = (unsigned)(r * PITCH + (ks + b_k8) * 2);
                ldsm2(bh[nf], sb + SM_BH + off);
                ldsm2(bl[nf], sb + SM_BL + off);
            }
#pragma unroll
            for (int mf = 0; mf < 4; mf++)
#pragma unroll
                for (int nf = 0; nf < 4; nf++) {
                    mma_bf16(acc[mf][nf], ah[mf], bh[nf]);
                    mma_bf16(acc[mf][nf], ah[mf], bl[nf]);
                    mma_bf16(acc[mf][nf], al[mf], bh[nf]);
                }
        }
        __syncthreads();
    }

    // ---- epilogue: c-frag layout (g = lane>>2 row, t = lane&3 col pair)
    const int g = lane >> 2;
    const int t = lane & 3;
#pragma unroll
    for (int mf = 0; mf < 4; mf++) {
#pragma unroll
        for (int nf = 0; nf < 4; nf++) {
            int row0 = brow + wm * 64 + mf * 16 + g;
            int row1 = row0 + 8;
            int col  = wn * 32 + nf * 8 + t * 2;
            if (row0 < N) {
                float2 v = make_float2(acc[mf][nf][0] + __ldg(bias + col),
                                       acc[mf][nf][1] + __ldg(bias + col + 1));
                *(float2*)(g_x + (long long)row0 * 128 + col) = v;
            }
            if (row1 < N) {
                float2 v = make_float2(acc[mf][nf][2] + __ldg(bias + col),
                                       acc[mf][nf][3] + __ldg(bias + col + 1));
                *(float2*)(g_x + (long long)row1 * 128 + col) = v;
            }
        }
    }
}

// ---------------------------------------------------------------------------
// Kernel 2: h1 = feat @ W1^T + b1, h2 = feat @ W2^T + b2   (one warp / node)
// ---------------------------------------------------------------------------
__global__ __launch_bounds__(256) void h_kernel(
    const float* __restrict__ feat,
    const float* __restrict__ W1, const float* __restrict__ b1,
    const float* __restrict__ W2, const float* __restrict__ b2,
    int N)
{
    int warp = (blockIdx.x * blockDim.x + threadIdx.x) >> 5;
    if (warp >= N) return;
    int lane = threadIdx.x & 31;

    float a[4] = {0.f, 0.f, 0.f, 0.f};
    float b[4] = {0.f, 0.f, 0.f, 0.f};
    const float* frow = feat + (long long)warp * 256;
#pragma unroll
    for (int kk = 0; kk < 8; kk++) {
        int k   = lane + kk * 32;
        float f = frow[k];
#pragma unroll
        for (int j = 0; j < 4; j++) {
            a[j] = fmaf(f, __ldg(W1 + j * 256 + k), a[j]);
            b[j] = fmaf(f, __ldg(W2 + j * 256 + k), b[j]);
        }
    }
#pragma unroll
    for (int off = 16; off; off >>= 1) {
#pragma unroll
        for (int j = 0; j < 4; j++) {
            a[j] += __shfl_xor_sync(0xFFFFFFFFu, a[j], off);
            b[j] += __shfl_xor_sync(0xFFFFFFFFu, b[j], off);
        }
    }
    if (lane == 0) {
        g_h1[warp] = make_float4(a[0] + b1[0], a[1] + b1[1], a[2] + b1[2], a[3] + b1[3]);
        g_h2[warp] = make_float4(b[0] + b2[0], b[1] + b2[1], b[2] + b2[2], b[3] + b2[3]);
    }
}

// ---------------------------------------------------------------------------
// CSR build: zero, count, PARALLEL 3-pass scan, scatter
// ---------------------------------------------------------------------------
__global__ void zero_cnt_kernel(int N)
{
    int i = blockIdx.x * blockDim.x + threadIdx.x;
    if (i < N) g_cnt[i] = 0;
}

__global__ void count_kernel(const int* __restrict__ ei, int E)
{
    int e = blockIdx.x * blockDim.x + threadIdx.x;
    if (e < E) atomicAdd(&g_cnt[ei[e]], 1);
}

__global__ __launch_bounds__(256) void scan1_kernel(int N)
{
    __shared__ int wsum[8];
    const int b = blockIdx.x;
    const int tid = threadIdx.x, lane = tid & 31, wid = tid >> 5;
    const int base = b * 1024 + tid * 4;

    int v0 = (base + 0 < N) ? g_cnt[base + 0] : 0;
    int v1 = (base + 1 < N) ? g_cnt[base + 1] : 0;
    int v2 = (base + 2 < N) ? g_cnt[base + 2] : 0;
    int v3 = (base + 3 < N) ? g_cnt[base + 3] : 0;
    int t = v0 + v1 + v2 + v3;

    int x = t;
#pragma unroll
    for (int o = 1; o < 32; o <<= 1) {
        int y = __shfl_up_sync(0xFFFFFFFFu, x, o);
        if (lane >= o) x += y;
    }
    if (lane == 31) wsum[wid] = x;
    __syncthreads();
    if (wid == 0 && lane < 8) {
        int s = wsum[lane];
#pragma unroll
        for (int o = 1; o < 8; o <<= 1) {
            int y = __shfl_up_sync(0xFFu, s, o);
            if (lane >= o) s += y;
        }
        wsum[lane] = s;
    }
    __syncthreads();

    int excl = ((wid > 0) ? wsum[wid - 1] : 0) + x - t;
    if (base + 0 < N) g_off[base + 0] = excl;
    if (base + 1 < N) g_off[base + 1] = excl + v0;
    if (base + 2 < N) g_off[base + 2] = excl + v0 + v1;
    if (base + 3 < N) g_off[base + 3] = excl + v0 + v1 + v2;
    if (tid == 0) g_bsum[b] = wsum[7];
}

__global__ void scan2_kernel(int NB)
{
    __shared__ int ws[2];
    const int tid = threadIdx.x, lane = tid & 31, wid = tid >> 5;
    int v = (tid < NB) ? g_bsum[tid] : 0;
    int x = v;
#pragma unroll
    for (int o = 1; o < 32; o <<= 1) {
        int y = __shfl_up_sync(0xFFFFFFFFu, x, o);
        if (lane >= o) x += y;
    }
    if (lane == 31) ws[wid] = x;
    __syncthreads();
    int incl = x + ((wid == 1) ? ws[0] : 0);
    if (tid < NB) g_bsum[tid] = incl - v;
}

__global__ void scan3_kernel(int N, int E)
{
    int i = blockIdx.x * blockDim.x + threadIdx.x;
    if (i < N) {
        int o = g_off[i] + g_bsum[i >> 10];
        g_off[i] = o;
        g_cur[i] = o;
    }
    if (i == 0) g_off[N] = E;
}

__global__ void scatter_kernel(const int* __restrict__ ei, int E)
{
    int e = blockIdx.x * blockDim.x + threadIdx.x;
    if (e < E) {
        int s = ei[e];
        int d = ei[E + e];
        int pos = atomicAdd(&g_cur[s], 1);
        g_sdst[pos] = d;
    }
}

// ---------------------------------------------------------------------------
// Kernel 4: aggregate.  One warp per node, no atomics, 2-edge ILP.
// (Round-4 known-good version, unchanged.)
// ---------------------------------------------------------------------------
__global__ __launch_bounds__(256) void agg_kernel(
    const float* __restrict__ eps,
    float* __restrict__ OUT,
    int N)
{
    int node = (blockIdx.x * blockDim.x + threadIdx.x) >> 5;
    if (node >= N) return;
    int lane = threadIdx.x & 31;
    int head = lane >> 3;           // 4 heads, 8 lanes each
    int j    = lane * 4;            // feature offset (float4)

    float4 ha = g_h1[node];
    float ha_h = (head < 2) ? (head == 0 ? ha.x : ha.y)
                            : (head == 2 ? ha.z : ha.w);

    int i   = g_off[node];
    int end = g_off[node + 1];

    float4 acc0 = make_float4(0.f, 0.f, 0.f, 0.f);
    float4 acc1 = make_float4(0.f, 0.f, 0.f, 0.f);

    for (; i + 2 <= end; i += 2) {
        int d0 = __ldg(&g_sdst[i]);
        int d1 = __ldg(&g_sdst[i + 1]);
        float4 hb0 = g_h2[d0];
        float4 hb1 = g_h2[d1];
        float v0 = ha_h + ((head < 2) ? (head == 0 ? hb0.x : hb0.y)
                                      : (head == 2 ? hb0.z : hb0.w));
        float v1 = ha_h + ((head < 2) ? (head == 0 ? hb1.x : hb1.y)
                                      : (head == 2 ? hb1.z : hb1.w));
        if (v0 > 0.f) {
            float4 xv = *(const float4*)(g_x + (long long)d0 * 128 + j);
            acc0.x = fmaf(v0, xv.x, acc0.x);
            acc0.y = fmaf(v0, xv.y, acc0.y);
            acc0.z = fmaf(v0, xv.z, acc0.z);
            acc0.w = fmaf(v0, xv.w, acc0.w);
        }
        if (v1 > 0.f) {
            float4 xv = *(const float4*)(g_x + (long long)d1 * 128 + j);
            acc1.x = fmaf(v1, xv.x, acc1.x);
            acc1.y = fmaf(v1, xv.y, acc1.y);
            acc1.z = fmaf(v1, xv.z, acc1.z);
            acc1.w = fmaf(v1, xv.w, acc1.w);
        }
    }
    if (i < end) {  // tail edge
        int d0 = __ldg(&g_sdst[i]);
        float4 hb0 = g_h2[d0];
        float v0 = ha_h + ((head < 2) ? (head == 0 ? hb0.x : hb0.y)
                                      : (head == 2 ? hb0.z : hb0.w));
        if (v0 > 0.f) {
            float4 xv = *(const float4*)(g_x + (long long)d0 * 128 + j);
            acc0.x = fmaf(v0, xv.x, acc0.x);
            acc0.y = fmaf(v0, xv.y, acc0.y);
            acc0.z = fmaf(v0, xv.z, acc0.z);
            acc0.w = fmaf(v0, xv.w, acc0.w);
        }
    }

    float e0 = eps[0];
    float4 xs = *(const float4*)(g_x + (long long)node * 128 + j);
    float4 o;
    o.x = fmaf(e0, xs.x, acc0.x + acc1.x);
    o.y = fmaf(e0, xs.y, acc0.y + acc1.y);
    o.z = fmaf(e0, xs.z, acc0.z + acc1.z);
    o.w = fmaf(e0, xs.w, acc0.w + acc1.w);
    *(float4*)(OUT + (long long)node * 128 + j) = o;
}

// ---------------------------------------------------------------------------
extern "C" void kernel_launch(void* const* d_in, const int* in_sizes, int n_in,
                              void* d_out, int out_size)
{
    const float* feat  = (const float*)d_in[0];
    const int*   ei    = (const int*)d_in[1];
    const float* W_mlp = (const float*)d_in[2];
    const float* b_mlp = (const float*)d_in[3];
    const float* W1    = (const float*)d_in[4];
    const float* b1    = (const float*)d_in[5];
    const float* W2    = (const float*)d_in[6];
    const float* b2    = (const float*)d_in[7];
    const float* eps   = (const float*)d_in[8];

    const int N = in_sizes[0] / 256;
    const int E = in_sizes[1] / 2;
    float* out = (float*)d_out;

    // One-time stream/event/attr setup (host objects, no device mem)
    static cudaStream_t s_side = nullptr;
    static cudaEvent_t  ev_fork = nullptr, ev_join = nullptr;
    if (!s_side) {
        cudaStreamCreateWithFlags(&s_side, cudaStreamNonBlocking);
        cudaEventCreateWithFlags(&ev_fork, cudaEventDisableTiming);
        cudaEventCreateWithFlags(&ev_join, cudaEventDisableTiming);
        cudaFuncSetAttribute(gemm_mma_kernel,
                             cudaFuncAttributeMaxDynamicSharedMemorySize, SM_GEMM);
    }

    const int NB = (N + 1023) / 1024;   // scan blocks (<=64 for N<=65536)

    // Fork: h projections + CSR build on side stream.
    cudaEventRecord(ev_fork, 0);
    cudaStreamWaitEvent(s_side, ev_fork, 0);

    h_kernel<<<(N + 7) / 8, 256, 0, s_side>>>(feat, W1, b1, W2, b2, N);
    zero_cnt_kernel<<<(N + 511) / 512, 512, 0, s_side>>>(N);
    count_kernel<<<(E + 255) / 256, 256, 0, s_side>>>(ei, E);
    scan1_kernel<<<NB, 256, 0, s_side>>>(N);
    scan2_kernel<<<1, 64, 0, s_side>>>(NB);
    scan3_kernel<<<(N + 255) / 256, 256, 0, s_side>>>(N, E);
    scatter_kernel<<<(E + 255) / 256, 256, 0, s_side>>>(ei, E);
    cudaEventRecord(ev_join, s_side);

    // Dense chain on capture (NULL) stream: tensor-pipe GEMM (HMMA).
    gemm_mma_kernel<<<(N + 127) / 128, 256, SM_GEMM>>>(feat, W_mlp, b_mlp, N);

    // Join, then atomic-free aggregation + epilogue.
    cudaStreamWaitEvent(0, ev_join, 0);
    agg_kernel<<<(N + 7) / 8, 256>>>(eps, out, N);
}